// round 3
// baseline (speedup 1.0000x reference)
#include <cuda_runtime.h>

#define BQ 16384

// ---------------- scratch (device globals; no runtime allocation) ----------------
__device__ float g_h0 [BQ * 256];       // deep layer0 out
__device__ float g_h1d[BQ * 128];       // deep layer1 out
__device__ float g_hid[BQ * 64 * 32];   // CIN hidden (relu(out0[:, :64, :]))
__device__ float g_ds [BQ * 64];        // sum_d relu(out0[:, 64:, :])
__device__ float g_s1 [BQ * 128];       // sum_d relu(out1)
__device__ float g_aux1[BQ];            // linear part of aux

// ---------------- linear: aux1[b] = dot(x[b], lin_w) + lin_b ----------------
__global__ __launch_bounds__(256)
void lin_kernel(const float* __restrict__ x, const float* __restrict__ lw,
                const float* __restrict__ lb) {
    int warp = threadIdx.x >> 5, lane = threadIdx.x & 31;
    int b = blockIdx.x * 8 + warp;
    const float* xr = x + (size_t)b * 1280;
    float s = 0.f;
    for (int k = lane; k < 1280; k += 32) s += xr[k] * lw[k];
    #pragma unroll
    for (int off = 16; off; off >>= 1) s += __shfl_xor_sync(0xffffffffu, s, off);
    if (lane == 0) g_aux1[b] = s + lb[0];
}

// ---------------- deep layer: out = relu(LN(A @ W^T + bias)) ----------------
// 256 threads as 16(ty: rows) x 16(tx: cols). Full N per block so LN is in-register.
template<int N, int ROWS, int TM, int TN, int K>
__global__ __launch_bounds__(256)
void deep_kernel(const float* __restrict__ A, const float* __restrict__ W,
                 const float* __restrict__ bias, const float* __restrict__ gam,
                 const float* __restrict__ bet, float* __restrict__ out) {
    __shared__ float As[16][ROWS];
    __shared__ float Bs[16][N];
    const int tid = threadIdx.x;
    const int tx = tid & 15, ty = tid >> 4;
    const int r0 = blockIdx.x * ROWS;

    float acc[TM][TN];
    #pragma unroll
    for (int i = 0; i < TM; i++)
        #pragma unroll
        for (int j = 0; j < TN; j++) acc[i][j] = 0.f;

    for (int k0 = 0; k0 < K; k0 += 16) {
        for (int i = tid; i < ROWS * 4; i += 256) {
            int r = i >> 2, q = (i & 3) * 4;
            float4 v = *(const float4*)(A + (size_t)(r0 + r) * K + k0 + q);
            As[q + 0][r] = v.x; As[q + 1][r] = v.y;
            As[q + 2][r] = v.z; As[q + 3][r] = v.w;
        }
        for (int i = tid; i < N * 4; i += 256) {
            int n = i >> 2, q = (i & 3) * 4;
            float4 v = *(const float4*)(W + (size_t)n * K + k0 + q);
            Bs[q + 0][n] = v.x; Bs[q + 1][n] = v.y;
            Bs[q + 2][n] = v.z; Bs[q + 3][n] = v.w;
        }
        __syncthreads();
        #pragma unroll 4
        for (int kc = 0; kc < 16; kc++) {
            float a[TM], bv[TN];
            #pragma unroll
            for (int i = 0; i < TM; i++) a[i] = As[kc][ty * TM + i];
            #pragma unroll
            for (int j = 0; j < TN; j++) bv[j] = Bs[kc][tx * TN + j];
            #pragma unroll
            for (int i = 0; i < TM; i++)
                #pragma unroll
                for (int j = 0; j < TN; j++)
                    acc[i][j] = fmaf(a[i], bv[j], acc[i][j]);
        }
        __syncthreads();
    }

    // bias + LayerNorm (across 16 tx lanes) + relu + store
    float bx[TN], gx[TN], btx[TN];
    #pragma unroll
    for (int j = 0; j < TN; j++) {
        bx[j] = bias[tx * TN + j]; gx[j] = gam[tx * TN + j]; btx[j] = bet[tx * TN + j];
    }
    #pragma unroll
    for (int i = 0; i < TM; i++) {
        float ps = 0.f, pq = 0.f;
        #pragma unroll
        for (int j = 0; j < TN; j++) {
            float v = acc[i][j] + bx[j];
            acc[i][j] = v; ps += v; pq += v * v;
        }
        #pragma unroll
        for (int off = 8; off; off >>= 1) {
            ps += __shfl_xor_sync(0xffffffffu, ps, off, 16);
            pq += __shfl_xor_sync(0xffffffffu, pq, off, 16);
        }
        float mu = ps * (1.0f / N);
        float var = pq * (1.0f / N) - mu * mu;
        float rs = rsqrtf(var + 1e-5f);
        int r = r0 + ty * TM + i;
        #pragma unroll
        for (int j = 0; j < TN; j++) {
            int n = tx * TN + j;
            float v = (acc[i][j] - mu) * rs * gx[j] + btx[j];
            out[(size_t)r * N + n] = fmaxf(v, 0.f);
        }
    }
}

// ---------------- CIN layer 0 ----------------
// out0[b,o,d] = sum_{m,n} W0[o, m*40+n] * x[b,m,d] * x[b,n,d]
// Per block: 4 batches (128 cols = 4 g x 32 d) x all 128 o. 8x8 register tile.
__global__ __launch_bounds__(256)
void cin0_kernel(const float* __restrict__ emb, const float* __restrict__ W,
                 const float* __restrict__ bias) {
    extern __shared__ float cs[];
    float* xs = cs;              // 4*1280
    float* Ws = xs + 5120;       // 32*128  [kc][o]
    float* Zs = Ws + 4096;       // 32*128  [kc][c]
    const int tid = threadIdx.x;
    const int tx = tid & 15, ty = tid >> 4;
    const int b0 = blockIdx.x * 4;

    const float4* embv = (const float4*)(emb + (size_t)b0 * 1280);
    for (int i = tid; i < 1280; i += 256) ((float4*)xs)[i] = embv[i];

    float acc[8][8];
    #pragma unroll
    for (int i = 0; i < 8; i++)
        #pragma unroll
        for (int j = 0; j < 8; j++) acc[i][j] = 0.f;

    const int zkc = tid >> 3;            // 0..31 (which k row of Z this thread fills)
    const int zc0 = (tid & 7) * 16;      // 16 consecutive cols
    const int zg  = zc0 >> 5;            // batch within group
    const int zd0 = zc0 & 31;            // 0 or 16
    const float* xz = xs + zg * 1280 + zd0;

    __syncthreads();

    for (int k0 = 0; k0 < 1600; k0 += 32) {
        // stage W chunk [32 kc][128 o]
        #pragma unroll
        for (int q = 0; q < 4; q++) {
            int idx = tid + 256 * q;
            int o = idx >> 3, qq = (idx & 7) * 4;
            float4 v = *(const float4*)(W + (size_t)o * 1600 + k0 + qq);
            Ws[(qq + 0) * 128 + o] = v.x; Ws[(qq + 1) * 128 + o] = v.y;
            Ws[(qq + 2) * 128 + o] = v.z; Ws[(qq + 3) * 128 + o] = v.w;
        }
        // build Z chunk: Z[kc][ (g,d) ] = x[g,m,d]*x[g,n,d]
        {
            int k = k0 + zkc;
            int m = k / 40;
            int n = k - m * 40;
            const float4* xm = (const float4*)(xz + m * 32);
            const float4* xn = (const float4*)(xz + n * 32);
            float4* zo = (float4*)(Zs + zkc * 128 + zc0);
            #pragma unroll
            for (int q = 0; q < 4; q++) {
                float4 a = xm[q], b = xn[q], r;
                r.x = a.x * b.x; r.y = a.y * b.y; r.z = a.z * b.z; r.w = a.w * b.w;
                zo[q] = r;
            }
        }
        __syncthreads();
        #pragma unroll 4
        for (int kc = 0; kc < 32; kc++) {
            float4 w0 = ((const float4*)(Ws + kc * 128))[ty * 2];
            float4 w1 = ((const float4*)(Ws + kc * 128))[ty * 2 + 1];
            float4 z0 = ((const float4*)(Zs + kc * 128))[tx * 2];
            float4 z1 = ((const float4*)(Zs + kc * 128))[tx * 2 + 1];
            float wv[8] = {w0.x, w0.y, w0.z, w0.w, w1.x, w1.y, w1.z, w1.w};
            float zv[8] = {z0.x, z0.y, z0.z, z0.w, z1.x, z1.y, z1.z, z1.w};
            #pragma unroll
            for (int i = 0; i < 8; i++)
                #pragma unroll
                for (int j = 0; j < 8; j++)
                    acc[i][j] = fmaf(wv[i], zv[j], acc[i][j]);
        }
        __syncthreads();
    }

    // epilogue: o<64 -> hidden tensor, o>=64 -> direct sum over d
    const int g = tx >> 2, d0 = (tx & 3) * 8;
    const int bb = b0 + g;
    if (ty < 8) {
        #pragma unroll
        for (int i = 0; i < 8; i++) {
            int o = ty * 8 + i;
            float bo = bias[o];
            float4 v0, v1;
            v0.x = fmaxf(acc[i][0] + bo, 0.f); v0.y = fmaxf(acc[i][1] + bo, 0.f);
            v0.z = fmaxf(acc[i][2] + bo, 0.f); v0.w = fmaxf(acc[i][3] + bo, 0.f);
            v1.x = fmaxf(acc[i][4] + bo, 0.f); v1.y = fmaxf(acc[i][5] + bo, 0.f);
            v1.z = fmaxf(acc[i][6] + bo, 0.f); v1.w = fmaxf(acc[i][7] + bo, 0.f);
            float4* dst = (float4*)(g_hid + (size_t)bb * 2048 + o * 32 + d0);
            dst[0] = v0; dst[1] = v1;
        }
    } else {
        #pragma unroll
        for (int i = 0; i < 8; i++) {
            int o = ty * 8 + i;  // 64..127
            float bo = bias[o];
            float s = 0.f;
            #pragma unroll
            for (int j = 0; j < 8; j++) s += fmaxf(acc[i][j] + bo, 0.f);
            s += __shfl_xor_sync(0xffffffffu, s, 1, 4);
            s += __shfl_xor_sync(0xffffffffu, s, 2, 4);
            if ((tx & 3) == 0) g_ds[(size_t)bb * 64 + (o - 64)] = s;
        }
    }
}

// ---------------- CIN layer 1 ----------------
// out1[b,o,d] = sum_{m<40,n<64} W1[o, m*64+n] * x[b,m,d] * hid[b,n,d]
__global__ __launch_bounds__(256)
void cin1_kernel(const float* __restrict__ emb, const float* __restrict__ W,
                 const float* __restrict__ bias) {
    extern __shared__ float cs[];
    float* xs = cs;              // 5120
    float* hs = xs + 5120;       // 8192
    float* Ws = hs + 8192;       // 4096
    float* Zs = Ws + 4096;       // 4096
    const int tid = threadIdx.x;
    const int tx = tid & 15, ty = tid >> 4;
    const int b0 = blockIdx.x * 4;

    const float4* embv = (const float4*)(emb + (size_t)b0 * 1280);
    for (int i = tid; i < 1280; i += 256) ((float4*)xs)[i] = embv[i];
    const float4* hidv = (const float4*)(g_hid + (size_t)b0 * 2048);
    for (int i = tid; i < 2048; i += 256) ((float4*)hs)[i] = hidv[i];

    float acc[8][8];
    #pragma unroll
    for (int i = 0; i < 8; i++)
        #pragma unroll
        for (int j = 0; j < 8; j++) acc[i][j] = 0.f;

    const int zkc = tid >> 3;
    const int zc0 = (tid & 7) * 16;
    const int zg  = zc0 >> 5;
    const int zd0 = zc0 & 31;
    const float* xz = xs + zg * 1280 + zd0;
    const float* hz = hs + zg * 2048 + zd0;

    __syncthreads();

    for (int k0 = 0; k0 < 2560; k0 += 32) {
        #pragma unroll
        for (int q = 0; q < 4; q++) {
            int idx = tid + 256 * q;
            int o = idx >> 3, qq = (idx & 7) * 4;
            float4 v = *(const float4*)(W + (size_t)o * 2560 + k0 + qq);
            Ws[(qq + 0) * 128 + o] = v.x; Ws[(qq + 1) * 128 + o] = v.y;
            Ws[(qq + 2) * 128 + o] = v.z; Ws[(qq + 3) * 128 + o] = v.w;
        }
        {
            int k = k0 + zkc;
            int m = k >> 6;
            int n = k & 63;
            const float4* xm = (const float4*)(xz + m * 32);
            const float4* hn = (const float4*)(hz + n * 32);
            float4* zo = (float4*)(Zs + zkc * 128 + zc0);
            #pragma unroll
            for (int q = 0; q < 4; q++) {
                float4 a = xm[q], b = hn[q], r;
                r.x = a.x * b.x; r.y = a.y * b.y; r.z = a.z * b.z; r.w = a.w * b.w;
                zo[q] = r;
            }
        }
        __syncthreads();
        #pragma unroll 4
        for (int kc = 0; kc < 32; kc++) {
            float4 w0 = ((const float4*)(Ws + kc * 128))[ty * 2];
            float4 w1 = ((const float4*)(Ws + kc * 128))[ty * 2 + 1];
            float4 z0 = ((const float4*)(Zs + kc * 128))[tx * 2];
            float4 z1 = ((const float4*)(Zs + kc * 128))[tx * 2 + 1];
            float wv[8] = {w0.x, w0.y, w0.z, w0.w, w1.x, w1.y, w1.z, w1.w};
            float zv[8] = {z0.x, z0.y, z0.z, z0.w, z1.x, z1.y, z1.z, z1.w};
            #pragma unroll
            for (int i = 0; i < 8; i++)
                #pragma unroll
                for (int j = 0; j < 8; j++)
                    acc[i][j] = fmaf(wv[i], zv[j], acc[i][j]);
        }
        __syncthreads();
    }

    const int g = tx >> 2;
    const int bb = b0 + g;
    #pragma unroll
    for (int i = 0; i < 8; i++) {
        int o = ty * 8 + i;
        float bo = bias[o];
        float s = 0.f;
        #pragma unroll
        for (int j = 0; j < 8; j++) s += fmaxf(acc[i][j] + bo, 0.f);
        s += __shfl_xor_sync(0xffffffffu, s, 1, 4);
        s += __shfl_xor_sync(0xffffffffu, s, 2, 4);
        if ((tx & 3) == 0) g_s1[(size_t)bb * 128 + o] = s;
    }
}

// ---------------- final aux: aux = aux1 + [ds | s1] . cin_out_w + cin_out_b ----------------
__global__ __launch_bounds__(256)
void aux_final(const float* __restrict__ cw, const float* __restrict__ cb,
               float* __restrict__ out) {
    int warp = threadIdx.x >> 5, lane = threadIdx.x & 31;
    int b = blockIdx.x * 8 + warp;
    float s = 0.f;
    for (int j = lane; j < 64; j += 32)  s += g_ds[(size_t)b * 64 + j]  * cw[j];
    for (int j = lane; j < 128; j += 32) s += g_s1[(size_t)b * 128 + j] * cw[64 + j];
    #pragma unroll
    for (int off = 16; off; off >>= 1) s += __shfl_xor_sync(0xffffffffu, s, off);
    if (lane == 0) out[(size_t)BQ * 64 + b] = g_aux1[b] + s + cb[0];
}

// ---------------- launcher ----------------
extern "C" void kernel_launch(void* const* d_in, const int* in_sizes, int n_in,
                              void* d_out, int out_size) {
    const float* x       = (const float*)d_in[0];
    const float* emb     = (const float*)d_in[1];
    const float* lin_w   = (const float*)d_in[2];
    const float* lin_b   = (const float*)d_in[3];
    const float* conv_w0 = (const float*)d_in[4];
    const float* conv_b0 = (const float*)d_in[5];
    const float* conv_w1 = (const float*)d_in[6];
    const float* conv_b1 = (const float*)d_in[7];
    const float* cow     = (const float*)d_in[8];
    const float* cob     = (const float*)d_in[9];
    const float* dw0     = (const float*)d_in[10];
    const float* db0     = (const float*)d_in[11];
    const float* lg0     = (const float*)d_in[12];
    const float* lb0     = (const float*)d_in[13];
    const float* dw1     = (const float*)d_in[14];
    const float* db1     = (const float*)d_in[15];
    const float* lg1     = (const float*)d_in[16];
    const float* lb1     = (const float*)d_in[17];
    const float* dw2     = (const float*)d_in[18];
    const float* db2     = (const float*)d_in[19];
    const float* lg2     = (const float*)d_in[20];
    const float* lb2     = (const float*)d_in[21];
    float* out = (float*)d_out;

    float *h0, *h1d;
    cudaGetSymbolAddress((void**)&h0, g_h0);
    cudaGetSymbolAddress((void**)&h1d, g_h1d);

    cudaFuncSetAttribute(cin0_kernel, cudaFuncAttributeMaxDynamicSharedMemorySize, 53248);
    cudaFuncSetAttribute(cin1_kernel, cudaFuncAttributeMaxDynamicSharedMemorySize, 86016);

    lin_kernel<<<BQ / 8, 256>>>(x, lin_w, lin_b);
    deep_kernel<256, 32, 2, 16, 1280><<<BQ / 32, 256>>>(x, dw0, db0, lg0, lb0, h0);
    deep_kernel<128, 64, 4, 8, 256><<<BQ / 64, 256>>>(h0, dw1, db1, lg1, lb1, h1d);
    deep_kernel<64, 128, 8, 4, 128><<<BQ / 128, 256>>>(h1d, dw2, db2, lg2, lb2, out);
    cin0_kernel<<<BQ / 4, 256, 53248>>>(emb, conv_w0, conv_b0);
    cin1_kernel<<<BQ / 4, 256, 86016>>>(emb, conv_w1, conv_b1);
    aux_final<<<BQ / 8, 256>>>(cow, cob, out);
}

// round 7
// speedup vs baseline: 1.9028x; 1.9028x over previous
#include <cuda_runtime.h>
#include <cuda_bf16.h>
#include <cstdint>

#define BQ 16384

// ---------------- scratch (device globals; no runtime allocation) ----------------
__device__ __align__(16) float g_h0 [BQ * 256];
__device__ __align__(16) float g_h1d[BQ * 128];
__device__ __align__(16) float g_hid[BQ * 64 * 32];
__device__ __align__(16) float g_ds [BQ * 64];
__device__ __align__(16) float g_s1 [BQ * 128];
__device__ __align__(16) float g_aux1[BQ];
// split-bf16 W, stored as pre-swizzled 16KB chunk tiles: [chunk][sw(o*128+kk*2)]
__device__ __align__(16) __nv_bfloat16 g_w0h[128 * 1600];
__device__ __align__(16) __nv_bfloat16 g_w0l[128 * 1600];
__device__ __align__(16) __nv_bfloat16 g_w1h[128 * 2560];
__device__ __align__(16) __nv_bfloat16 g_w1l[128 * 2560];

// ---------------- helpers ----------------
__device__ __forceinline__ uint32_t smem_to_u32(const void* p) {
    uint32_t a;
    asm("{ .reg .u64 t; cvta.to.shared.u64 t, %1; cvt.u32.u64 %0, t; }" : "=r"(a) : "l"(p));
    return a;
}
__device__ __forceinline__ uint32_t sw128(uint32_t off) { return off ^ ((off >> 3) & 0x70); }

// baseline-PTX tensor ops (legal on plain sm_103)
__device__ __forceinline__ void ldsm4(uint32_t* r, uint32_t addr) {
    asm volatile("ldmatrix.sync.aligned.m8n8.x4.shared.b16 {%0,%1,%2,%3}, [%4];"
                 : "=r"(r[0]), "=r"(r[1]), "=r"(r[2]), "=r"(r[3]) : "r"(addr));
}
__device__ __forceinline__ void mma16816(float* d, const uint32_t* a, uint32_t b0, uint32_t b1) {
    asm volatile("mma.sync.aligned.m16n8k16.row.col.f32.bf16.bf16.f32 "
                 "{%0,%1,%2,%3}, {%4,%5,%6,%7}, {%8,%9}, {%0,%1,%2,%3};"
                 : "+f"(d[0]), "+f"(d[1]), "+f"(d[2]), "+f"(d[3])
                 : "r"(a[0]), "r"(a[1]), "r"(a[2]), "r"(a[3]), "r"(b0), "r"(b1));
}

// ---------------- W split+tile precompute ----------------
__global__ __launch_bounds__(256)
void wsplit_kernel(const float* __restrict__ w, __nv_bfloat16* __restrict__ hi,
                   __nv_bfloat16* __restrict__ lo, int K) {
    int t = blockIdx.x * 256 + threadIdx.x;
    int total = 128 * (K >> 1);
    if (t >= total) return;
    int hk = K >> 1;
    int o = t / hk, p = t - o * hk;
    int k = p * 2;
    float v0 = w[o * K + k], v1 = w[o * K + k + 1];
    __nv_bfloat16 h0 = __float2bfloat16(v0), h1 = __float2bfloat16(v1);
    __nv_bfloat16 l0 = __float2bfloat16(v0 - __bfloat162float(h0));
    __nv_bfloat16 l1 = __float2bfloat16(v1 - __bfloat162float(h1));
    int chunk = k >> 6, kk = k & 63;
    uint32_t off = chunk * 16384 + sw128((uint32_t)(o * 128 + kk * 2));
    uint32_t ph = (uint32_t)__bfloat16_as_ushort(h0) | ((uint32_t)__bfloat16_as_ushort(h1) << 16);
    uint32_t pl = (uint32_t)__bfloat16_as_ushort(l0) | ((uint32_t)__bfloat16_as_ushort(l1) << 16);
    *(uint32_t*)((char*)hi + off) = ph;
    *(uint32_t*)((char*)lo + off) = pl;
}

// ---------------- CIN tensor kernel (mma.sync, plain sm_103) ----------------
// LAYER 0: K=1600, k=m*40+n, z = x[m]*x[n];  LAYER 1: K=2560, k=m*64+n, z = x[m]*hid[n]
// out[o, c], c = g*32+d over 4 batches per CTA; split-bf16 3-pass compensation.
template<int LAYER>
__global__ __launch_bounds__(256)
void cin_mma_kernel(const float* __restrict__ emb,
                    const __nv_bfloat16* __restrict__ Wh,
                    const __nv_bfloat16* __restrict__ Wl,
                    const float* __restrict__ bias) {
    constexpr int K   = LAYER ? 2560 : 1600;
    constexpr int NCH = K / 64;
    constexpr int OFF_XS  = 1024;
    constexpr int OFF_HS  = 21504;
    constexpr int OFF_BUF = LAYER ? 54272 : 21504;

    extern __shared__ char smem[];
    const uint32_t sb = smem_to_u32(smem);
    const int tid = threadIdx.x, wid = tid >> 5, lane = tid & 31;
    const int b0 = blockIdx.x * 4;
    float* xs = (float*)(smem + OFF_XS);
    float* hs = (float*)(smem + OFF_HS);

    // load x (rotated: element (g,m,d) at xs[g*1280 + m*32 + ((d+m)&31)])
    const float* esrc = emb + (size_t)b0 * 1280;
    for (int e = tid; e < 5120; e += 256) {
        int g = e / 1280, r = e - g * 1280, m = r >> 5, d = r & 31;
        xs[g * 1280 + m * 32 + ((d + m) & 31)] = esrc[e];
    }
    if (LAYER == 1) {
        const float* hsrc = g_hid + (size_t)b0 * 2048;
        for (int e = tid; e < 8192; e += 256) {
            int g = e >> 11, r = e & 2047, n = r >> 5, d = r & 31;
            hs[g * 2048 + n * 32 + ((d + n) & 31)] = hsrc[e];
        }
    }
    __syncthreads();

    // Z-gen assignment: warp w -> g = w>>1, d-block = (w&1)*16; lane -> k-pair (2l,2l+1)
    const int zg = wid >> 1, zdb = (wid & 1) * 16;
    const float* xb = xs + zg * 1280;
    const float* hb = (LAYER ? hs + zg * 2048 : xb);

    // Warp wid computes rows o = wid*16..wid*16+15 across all 128 cols.
    float acc[16][4];
    #pragma unroll
    for (int j = 0; j < 16; j++)
        #pragma unroll
        for (int q = 0; q < 4; q++) acc[j][q] = 0.f;

    const uint32_t a_off_base = (uint32_t)((wid * 16 + (lane & 15)) * 128 + (lane >> 4) * 16);
    const int l8 = lane & 7, grp = lane >> 3;
    const uint32_t b_row = (uint32_t)((grp >> 1) * 8 + l8);
    const uint32_t b_kh = (uint32_t)((grp & 1) * 16);

    for (int ch = 0; ch < NCH; ch++) {
        const int buf = ch & 1;
        char* bufp = smem + OFF_BUF + buf * 65536;
        const int k0 = ch * 64;
        // A-fill: linear copy of pre-swizzled tiles (hi, lo)
        {
            const uint4* sh = (const uint4*)((const char*)Wh + ch * 16384);
            const uint4* sl = (const uint4*)((const char*)Wl + ch * 16384);
            uint4* dh = (uint4*)bufp;
            uint4* dl = (uint4*)(bufp + 16384);
            #pragma unroll
            for (int q = 0; q < 4; q++) {
                dh[tid + 256 * q] = sh[tid + 256 * q];
                dl[tid + 256 * q] = sl[tid + 256 * q];
            }
        }
        // B-fill: Z chunk split into bf16 hi/lo
        {
            char* Bh = bufp + 32768;
            char* Bl = bufp + 49152;
            int k = k0 + lane * 2;
            int m0, n0, m1, n1;
            if (LAYER == 0) { m0 = k / 40; n0 = k - m0 * 40; m1 = (k + 1) / 40; n1 = (k + 1) - m1 * 40; }
            else            { m0 = k >> 6; n0 = k & 63;      m1 = (k + 1) >> 6;  n1 = (k + 1) & 63; }
            const int am0 = m0 * 32, an0 = n0 * 32, am1 = m1 * 32, an1 = n1 * 32;
            #pragma unroll
            for (int i = 0; i < 16; i++) {
                int d = zdb + i;
                float z0 = xb[am0 + ((d + m0) & 31)] * hb[an0 + ((d + n0) & 31)];
                float z1 = xb[am1 + ((d + m1) & 31)] * hb[an1 + ((d + n1) & 31)];
                __nv_bfloat16 h0 = __float2bfloat16(z0), h1 = __float2bfloat16(z1);
                __nv_bfloat16 l0 = __float2bfloat16(z0 - __bfloat162float(h0));
                __nv_bfloat16 l1 = __float2bfloat16(z1 - __bfloat162float(h1));
                uint32_t phv = (uint32_t)__bfloat16_as_ushort(h0) | ((uint32_t)__bfloat16_as_ushort(h1) << 16);
                uint32_t plv = (uint32_t)__bfloat16_as_ushort(l0) | ((uint32_t)__bfloat16_as_ushort(l1) << 16);
                int c = wid * 16 + i;
                uint32_t off = sw128((uint32_t)(c * 128 + lane * 4));
                *(uint32_t*)(Bh + off) = phv;
                *(uint32_t*)(Bl + off) = plv;
            }
        }
        __syncthreads();

        const uint32_t abase_h = sb + OFF_BUF + buf * 65536;
        const uint32_t abase_l = abase_h + 16384;
        const uint32_t bbase_h = abase_h + 32768;
        const uint32_t bbase_l = abase_h + 49152;
        #pragma unroll
        for (int ks = 0; ks < 4; ks++) {
            uint32_t ah[4], al[4];
            uint32_t aoff = sw128(a_off_base + ks * 32);
            ldsm4(ah, abase_h + aoff);
            ldsm4(al, abase_l + aoff);
            #pragma unroll
            for (int nt = 0; nt < 8; nt++) {
                uint32_t boff = sw128((uint32_t)((nt * 16 + b_row) * 128 + ks * 32 + b_kh));
                uint32_t bh[4], bl[4];
                ldsm4(bh, bbase_h + boff);
                ldsm4(bl, bbase_l + boff);
                mma16816(acc[2 * nt],     ah, bh[0], bh[1]);
                mma16816(acc[2 * nt + 1], ah, bh[2], bh[3]);
                mma16816(acc[2 * nt],     ah, bl[0], bl[1]);
                mma16816(acc[2 * nt + 1], ah, bl[2], bl[3]);
                mma16816(acc[2 * nt],     al, bh[0], bh[1]);
                mma16816(acc[2 * nt + 1], al, bh[2], bh[3]);
            }
        }
        __syncthreads();
    }

    // epilogue: thread (grpID, qid) holds rows o = wid*16+grpID(+8), cols j*8 + qid*2 (+1)
    {
        const int grpID = lane >> 2, qid = lane & 3;
        if (LAYER == 0 && wid < 4) {
            #pragma unroll
            for (int half = 0; half < 2; half++) {
                int o = wid * 16 + grpID + half * 8;
                float bo = bias[o];
                #pragma unroll
                for (int j = 0; j < 16; j++) {
                    int c0 = j * 8 + qid * 2;
                    int g = c0 >> 5, d = c0 & 31;
                    float2 v;
                    v.x = fmaxf(acc[j][half * 2 + 0] + bo, 0.f);
                    v.y = fmaxf(acc[j][half * 2 + 1] + bo, 0.f);
                    *(float2*)(g_hid + (size_t)(b0 + g) * 2048 + o * 32 + d) = v;
                }
            }
        } else {
            #pragma unroll
            for (int half = 0; half < 2; half++) {
                int o = wid * 16 + grpID + half * 8;
                float bo = bias[o];
                #pragma unroll
                for (int g = 0; g < 4; g++) {
                    float s = 0.f;
                    #pragma unroll
                    for (int j = 4 * g; j < 4 * g + 4; j++)
                        s += fmaxf(acc[j][half * 2] + bo, 0.f) + fmaxf(acc[j][half * 2 + 1] + bo, 0.f);
                    s += __shfl_xor_sync(0xffffffffu, s, 1);
                    s += __shfl_xor_sync(0xffffffffu, s, 2);
                    if (qid == 0) {
                        if (LAYER == 0) g_ds[(size_t)(b0 + g) * 64 + (o - 64)] = s;
                        else            g_s1[(size_t)(b0 + g) * 128 + o] = s;
                    }
                }
            }
        }
    }
}

// ---------------- linear ----------------
__global__ __launch_bounds__(256)
void lin_kernel(const float* __restrict__ x, const float* __restrict__ lw,
                const float* __restrict__ lb) {
    int warp = threadIdx.x >> 5, lane = threadIdx.x & 31;
    int b = blockIdx.x * 8 + warp;
    const float* xr = x + (size_t)b * 1280;
    float s = 0.f;
    for (int k = lane; k < 1280; k += 32) s += xr[k] * lw[k];
    #pragma unroll
    for (int off = 16; off; off >>= 1) s += __shfl_xor_sync(0xffffffffu, s, off);
    if (lane == 0) g_aux1[b] = s + lb[0];
}

// ---------------- deep layer: out = relu(LN(A @ W^T + bias)) ----------------
template<int N, int ROWS, int TM, int TN, int K>
__global__ __launch_bounds__(256)
void deep_kernel(const float* __restrict__ A, const float* __restrict__ W,
                 const float* __restrict__ bias, const float* __restrict__ gam,
                 const float* __restrict__ bet, float* __restrict__ out) {
    __shared__ float As[16][ROWS];
    __shared__ float Bs[16][N];
    const int tid = threadIdx.x;
    const int tx = tid & 15, ty = tid >> 4;
    const int r0 = blockIdx.x * ROWS;

    float acc[TM][TN];
    #pragma unroll
    for (int i = 0; i < TM; i++)
        #pragma unroll
        for (int j = 0; j < TN; j++) acc[i][j] = 0.f;

    for (int k0 = 0; k0 < K; k0 += 16) {
        for (int i = tid; i < ROWS * 4; i += 256) {
            int r = i >> 2, q = (i & 3) * 4;
            float4 v = *(const float4*)(A + (size_t)(r0 + r) * K + k0 + q);
            As[q + 0][r] = v.x; As[q + 1][r] = v.y;
            As[q + 2][r] = v.z; As[q + 3][r] = v.w;
        }
        for (int i = tid; i < N * 4; i += 256) {
            int n = i >> 2, q = (i & 3) * 4;
            float4 v = *(const float4*)(W + (size_t)n * K + k0 + q);
            Bs[q + 0][n] = v.x; Bs[q + 1][n] = v.y;
            Bs[q + 2][n] = v.z; Bs[q + 3][n] = v.w;
        }
        __syncthreads();
        #pragma unroll 4
        for (int kc = 0; kc < 16; kc++) {
            float a[TM], bv[TN];
            #pragma unroll
            for (int i = 0; i < TM; i++) a[i] = As[kc][ty * TM + i];
            #pragma unroll
            for (int j = 0; j < TN; j++) bv[j] = Bs[kc][tx * TN + j];
            #pragma unroll
            for (int i = 0; i < TM; i++)
                #pragma unroll
                for (int j = 0; j < TN; j++)
                    acc[i][j] = fmaf(a[i], bv[j], acc[i][j]);
        }
        __syncthreads();
    }

    float bx[TN], gx[TN], btx[TN];
    #pragma unroll
    for (int j = 0; j < TN; j++) {
        bx[j] = bias[tx * TN + j]; gx[j] = gam[tx * TN + j]; btx[j] = bet[tx * TN + j];
    }
    #pragma unroll
    for (int i = 0; i < TM; i++) {
        float ps = 0.f, pq = 0.f;
        #pragma unroll
        for (int j = 0; j < TN; j++) {
            float v = acc[i][j] + bx[j];
            acc[i][j] = v; ps += v; pq += v * v;
        }
        #pragma unroll
        for (int off = 8; off; off >>= 1) {
            ps += __shfl_xor_sync(0xffffffffu, ps, off, 16);
            pq += __shfl_xor_sync(0xffffffffu, pq, off, 16);
        }
        float mu = ps * (1.0f / N);
        float var = pq * (1.0f / N) - mu * mu;
        float rs = rsqrtf(var + 1e-5f);
        int r = r0 + ty * TM + i;
        #pragma unroll
        for (int j = 0; j < TN; j++) {
            int n = tx * TN + j;
            float v = (acc[i][j] - mu) * rs * gx[j] + btx[j];
            out[(size_t)r * N + n] = fmaxf(v, 0.f);
        }
    }
}

// ---------------- final aux ----------------
__global__ __launch_bounds__(256)
void aux_final(const float* __restrict__ cw, const float* __restrict__ cb,
               float* __restrict__ out) {
    int warp = threadIdx.x >> 5, lane = threadIdx.x & 31;
    int b = blockIdx.x * 8 + warp;
    float s = 0.f;
    for (int j = lane; j < 64; j += 32)  s += g_ds[(size_t)b * 64 + j]  * cw[j];
    for (int j = lane; j < 128; j += 32) s += g_s1[(size_t)b * 128 + j] * cw[64 + j];
    #pragma unroll
    for (int off = 16; off; off >>= 1) s += __shfl_xor_sync(0xffffffffu, s, off);
    if (lane == 0) out[(size_t)BQ * 64 + b] = g_aux1[b] + s + cb[0];
}

// ---------------- launcher ----------------
extern "C" void kernel_launch(void* const* d_in, const int* in_sizes, int n_in,
                              void* d_out, int out_size) {
    const float* x       = (const float*)d_in[0];
    const float* emb     = (const float*)d_in[1];
    const float* lin_w   = (const float*)d_in[2];
    const float* lin_b   = (const float*)d_in[3];
    const float* conv_w0 = (const float*)d_in[4];
    const float* conv_b0 = (const float*)d_in[5];
    const float* conv_w1 = (const float*)d_in[6];
    const float* conv_b1 = (const float*)d_in[7];
    const float* cow     = (const float*)d_in[8];
    const float* cob     = (const float*)d_in[9];
    const float* dw0     = (const float*)d_in[10];
    const float* db0     = (const float*)d_in[11];
    const float* lg0     = (const float*)d_in[12];
    const float* lb0     = (const float*)d_in[13];
    const float* dw1     = (const float*)d_in[14];
    const float* db1     = (const float*)d_in[15];
    const float* lg1     = (const float*)d_in[16];
    const float* lb1     = (const float*)d_in[17];
    const float* dw2     = (const float*)d_in[18];
    const float* db2     = (const float*)d_in[19];
    const float* lg2     = (const float*)d_in[20];
    const float* lb2     = (const float*)d_in[21];
    float* out = (float*)d_out;

    float *h0, *h1d;
    __nv_bfloat16 *w0h, *w0l, *w1h, *w1l;
    cudaGetSymbolAddress((void**)&h0, g_h0);
    cudaGetSymbolAddress((void**)&h1d, g_h1d);
    cudaGetSymbolAddress((void**)&w0h, g_w0h);
    cudaGetSymbolAddress((void**)&w0l, g_w0l);
    cudaGetSymbolAddress((void**)&w1h, g_w1h);
    cudaGetSymbolAddress((void**)&w1l, g_w1l);

    cudaFuncSetAttribute(cin_mma_kernel<0>, cudaFuncAttributeMaxDynamicSharedMemorySize, 152576);
    cudaFuncSetAttribute(cin_mma_kernel<1>, cudaFuncAttributeMaxDynamicSharedMemorySize, 185344);

    wsplit_kernel<<<(128 * 800 + 255) / 256, 256>>>(conv_w0, w0h, w0l, 1600);
    wsplit_kernel<<<(128 * 1280 + 255) / 256, 256>>>(conv_w1, w1h, w1l, 2560);

    lin_kernel<<<BQ / 8, 256>>>(x, lin_w, lin_b);
    deep_kernel<256, 32, 2, 16, 1280><<<BQ / 32, 256>>>(x, dw0, db0, lg0, lb0, h0);
    deep_kernel<128, 64, 4, 8, 256><<<BQ / 64, 256>>>(h0, dw1, db1, lg1, lb1, h1d);
    deep_kernel<64, 128, 8, 4, 128><<<BQ / 128, 256>>>(h1d, dw2, db2, lg2, lb2, out);

    cin_mma_kernel<0><<<BQ / 4, 256, 152576>>>(emb, w0h, w0l, conv_b0);
    cin_mma_kernel<1><<<BQ / 4, 256, 185344>>>(emb, w1h, w1l, conv_b1);

    aux_final<<<BQ / 8, 256>>>(cow, cob, out);
}

// round 9
// speedup vs baseline: 2.7210x; 1.4300x over previous
#include <cuda_runtime.h>
#include <cuda_bf16.h>
#include <cstdint>

#define BQ 16384

// ---------------- scratch (device globals; no runtime allocation) ----------------
__device__ __align__(16) float g_h0 [BQ * 256];
__device__ __align__(16) float g_h1d[BQ * 128];
__device__ __align__(16) float g_hid[BQ * 64 * 32];
__device__ __align__(16) float g_ds [BQ * 64];
__device__ __align__(16) float g_s1 [BQ * 128];
__device__ __align__(16) float g_aux1[BQ];
// split-bf16 W, stored as pre-swizzled 16KB chunk tiles: [chunk][sw(o*128+kk*2)]
__device__ __align__(16) __nv_bfloat16 g_w0h[128 * 1600];
__device__ __align__(16) __nv_bfloat16 g_w0l[128 * 1600];
__device__ __align__(16) __nv_bfloat16 g_w1h[128 * 2560];
__device__ __align__(16) __nv_bfloat16 g_w1l[128 * 2560];

// ---------------- helpers ----------------
__device__ __forceinline__ uint32_t smem_to_u32(const void* p) {
    uint32_t a;
    asm("{ .reg .u64 t; cvta.to.shared.u64 t, %1; cvt.u32.u64 %0, t; }" : "=r"(a) : "l"(p));
    return a;
}
__device__ __forceinline__ uint32_t sw128(uint32_t off) { return off ^ ((off >> 3) & 0x70); }

__device__ __forceinline__ void ldsm4(uint32_t* r, uint32_t addr) {
    asm volatile("ldmatrix.sync.aligned.m8n8.x4.shared.b16 {%0,%1,%2,%3}, [%4];"
                 : "=r"(r[0]), "=r"(r[1]), "=r"(r[2]), "=r"(r[3]) : "r"(addr));
}
__device__ __forceinline__ void mma16816(float* d, const uint32_t* a, uint32_t b0, uint32_t b1) {
    asm volatile("mma.sync.aligned.m16n8k16.row.col.f32.bf16.bf16.f32 "
                 "{%0,%1,%2,%3}, {%4,%5,%6,%7}, {%8,%9}, {%0,%1,%2,%3};"
                 : "+f"(d[0]), "+f"(d[1]), "+f"(d[2]), "+f"(d[3])
                 : "r"(a[0]), "r"(a[1]), "r"(a[2]), "r"(a[3]), "r"(b0), "r"(b1));
}
__device__ __forceinline__ void cp_async16(uint32_t smem_addr, const void* gptr) {
    asm volatile("cp.async.cg.shared.global [%0], [%1], 16;" :: "r"(smem_addr), "l"(gptr));
}
#define CP_ASYNC_WAIT_ALL() \
    asm volatile("cp.async.commit_group;\ncp.async.wait_group 0;" ::: "memory")

// ---------------- W split+tile precompute ----------------
__global__ __launch_bounds__(256)
void wsplit_kernel(const float* __restrict__ w, __nv_bfloat16* __restrict__ hi,
                   __nv_bfloat16* __restrict__ lo, int K) {
    int t = blockIdx.x * 256 + threadIdx.x;
    int total = 128 * (K >> 1);
    if (t >= total) return;
    int hk = K >> 1;
    int o = t / hk, p = t - o * hk;
    int k = p * 2;
    float v0 = w[o * K + k], v1 = w[o * K + k + 1];
    __nv_bfloat16 h0 = __float2bfloat16(v0), h1 = __float2bfloat16(v1);
    __nv_bfloat16 l0 = __float2bfloat16(v0 - __bfloat162float(h0));
    __nv_bfloat16 l1 = __float2bfloat16(v1 - __bfloat162float(h1));
    int chunk = k >> 6, kk = k & 63;
    uint32_t off = chunk * 16384 + sw128((uint32_t)(o * 128 + kk * 2));
    uint32_t ph = (uint32_t)__bfloat16_as_ushort(h0) | ((uint32_t)__bfloat16_as_ushort(h1) << 16);
    uint32_t pl = (uint32_t)__bfloat16_as_ushort(l0) | ((uint32_t)__bfloat16_as_ushort(l1) << 16);
    *(uint32_t*)((char*)hi + off) = ph;
    *(uint32_t*)((char*)lo + off) = pl;
}

// ---------------- CIN tensor kernel (mma.sync, plain sm_103) ----------------
// LAYER 0: K=1600, k=m*40+n, z = x[m]*x[n] (xs in smem, rotated (d+m)&31)
// LAYER 1: K=2560, k=m*64+n, m==ch per chunk; z = x[g,ch,d]*hid[n,d]
//          (x row read from global broadcast; hs rotated (d+(n>>1))&31)
// out[o, c], c = g*32+d over 4 batches per CTA; split-bf16 3-pass compensation.
// Single 64KB buffer, cp.async A-fill, 2 CTAs/SM.
template<int LAYER>
__global__ __launch_bounds__(256, 2)
void cin_mma_kernel(const float* __restrict__ emb,
                    const __nv_bfloat16* __restrict__ Wh,
                    const __nv_bfloat16* __restrict__ Wl,
                    const float* __restrict__ bias) {
    constexpr int K   = LAYER ? 2560 : 1600;
    constexpr int NCH = K / 64;
    constexpr int OFF_XS  = 1024;                       // L0 xs (20KB)
    constexpr int OFF_HS  = 1024;                       // L1 hs (32KB)
    constexpr int OFF_BUF = LAYER ? (1024 + 32768) : (1024 + 20480);

    extern __shared__ char smem[];
    const uint32_t sb = smem_to_u32(smem);
    const int tid = threadIdx.x, wid = tid >> 5, lane = tid & 31;
    const int b0 = blockIdx.x * 4;
    float* xs = (float*)(smem + OFF_XS);
    float* hs = (float*)(smem + OFF_HS);

    if (LAYER == 0) {
        // x rotated: element (g,m,d) at xs[g*1280 + m*32 + ((d+m)&31)]
        const float* esrc = emb + (size_t)b0 * 1280;
        for (int e = tid; e < 5120; e += 256) {
            int g = e / 1280, r = e - g * 1280, m = r >> 5, d = r & 31;
            xs[g * 1280 + m * 32 + ((d + m) & 31)] = esrc[e];
        }
    } else {
        // hid rotated: (g,n,d) at hs[g*2048 + n*32 + ((d+(n>>1))&31)]
        const float* hsrc = g_hid + (size_t)b0 * 2048;
        for (int e = tid; e < 8192; e += 256) {
            int g = e >> 11, r = e & 2047, n = r >> 5, d = r & 31;
            hs[g * 2048 + n * 32 + ((d + (n >> 1)) & 31)] = hsrc[e];
        }
    }
    __syncthreads();

    // Z-gen assignment: warp w -> g = w>>1, d-block = (w&1)*16; lane -> k-pair (2l,2l+1)
    const int zg = wid >> 1, zdb = (wid & 1) * 16;
    const float* xb = xs + zg * 1280;                       // L0
    const float* hb = hs + zg * 2048;                       // L1
    const float* xgl = emb + (size_t)(b0 + zg) * 1280 + zdb; // L1 x row base

    // Warp wid computes rows o = wid*16..wid*16+15 across all 128 cols.
    float acc[16][4];
    #pragma unroll
    for (int j = 0; j < 16; j++)
        #pragma unroll
        for (int q = 0; q < 4; q++) acc[j][q] = 0.f;

    const uint32_t a_off_base = (uint32_t)((wid * 16 + (lane & 15)) * 128 + (lane >> 4) * 16);
    const int l8 = lane & 7, grp = lane >> 3;
    const uint32_t b_row = (uint32_t)((grp >> 1) * 8 + l8);
    const uint32_t b_kh = (uint32_t)((grp & 1) * 16);

    const uint32_t abase_h = sb + OFF_BUF;
    const uint32_t abase_l = abase_h + 16384;
    const uint32_t bbase_h = abase_h + 32768;
    const uint32_t bbase_l = abase_h + 49152;
    char* Bh = smem + OFF_BUF + 32768;
    char* Bl = smem + OFF_BUF + 49152;

    for (int ch = 0; ch < NCH; ch++) {
        // A-fill: cp.async linear copy of pre-swizzled tiles (hi, lo)
        {
            const char* sh = (const char*)Wh + ch * 16384;
            const char* sl = (const char*)Wl + ch * 16384;
            #pragma unroll
            for (int q = 0; q < 4; q++) {
                int idx = (tid + 256 * q) * 16;
                cp_async16(abase_h + idx, sh + idx);
                cp_async16(abase_l + idx, sl + idx);
            }
        }
        // B-fill: Z chunk split into bf16 hi/lo (overlaps cp.async latency)
        if (LAYER == 0) {
            int k = ch * 64 + lane * 2;
            int m0 = k / 40, n0 = k - m0 * 40;
            int m1 = (k + 1) / 40, n1 = (k + 1) - m1 * 40;
            const int am0 = m0 * 32, an0 = n0 * 32, am1 = m1 * 32, an1 = n1 * 32;
            #pragma unroll
            for (int i = 0; i < 16; i++) {
                int d = zdb + i;
                float z0 = xb[am0 + ((d + m0) & 31)] * xb[an0 + ((d + n0) & 31)];
                float z1 = xb[am1 + ((d + m1) & 31)] * xb[an1 + ((d + n1) & 31)];
                __nv_bfloat16 h0 = __float2bfloat16(z0), h1 = __float2bfloat16(z1);
                __nv_bfloat16 l0 = __float2bfloat16(z0 - __bfloat162float(h0));
                __nv_bfloat16 l1 = __float2bfloat16(z1 - __bfloat162float(h1));
                uint32_t phv = (uint32_t)__bfloat16_as_ushort(h0) | ((uint32_t)__bfloat16_as_ushort(h1) << 16);
                uint32_t plv = (uint32_t)__bfloat16_as_ushort(l0) | ((uint32_t)__bfloat16_as_ushort(l1) << 16);
                uint32_t off = sw128((uint32_t)((wid * 16 + i) * 128 + lane * 4));
                *(uint32_t*)(Bh + off) = phv;
                *(uint32_t*)(Bl + off) = plv;
            }
        } else {
            // m == ch for the whole chunk; x row broadcast from global
            float xv[16];
            const float4* xr = (const float4*)(xgl + ch * 32);
            #pragma unroll
            for (int q = 0; q < 4; q++) {
                float4 v = xr[q];
                xv[4 * q + 0] = v.x; xv[4 * q + 1] = v.y;
                xv[4 * q + 2] = v.z; xv[4 * q + 3] = v.w;
            }
            const int n0 = lane * 2, n1 = n0 + 1;
            const float* h0p = hb + n0 * 32;
            const float* h1p = hb + n1 * 32;
            #pragma unroll
            for (int i = 0; i < 16; i++) {
                int d = zdb + i;
                int rot = (d + lane) & 31;
                float z0 = xv[i] * h0p[rot];
                float z1 = xv[i] * h1p[rot];
                __nv_bfloat16 h0 = __float2bfloat16(z0), h1 = __float2bfloat16(z1);
                __nv_bfloat16 l0 = __float2bfloat16(z0 - __bfloat162float(h0));
                __nv_bfloat16 l1 = __float2bfloat16(z1 - __bfloat162float(h1));
                uint32_t phv = (uint32_t)__bfloat16_as_ushort(h0) | ((uint32_t)__bfloat16_as_ushort(h1) << 16);
                uint32_t plv = (uint32_t)__bfloat16_as_ushort(l0) | ((uint32_t)__bfloat16_as_ushort(l1) << 16);
                uint32_t off = sw128((uint32_t)((wid * 16 + i) * 128 + lane * 4));
                *(uint32_t*)(Bh + off) = phv;
                *(uint32_t*)(Bl + off) = plv;
            }
        }
        CP_ASYNC_WAIT_ALL();
        __syncthreads();

        #pragma unroll
        for (int ks = 0; ks < 4; ks++) {
            uint32_t ah[4], al[4];
            uint32_t aoff = sw128(a_off_base + ks * 32);
            ldsm4(ah, abase_h + aoff);
            ldsm4(al, abase_l + aoff);
            #pragma unroll
            for (int nt = 0; nt < 8; nt++) {
                uint32_t boff = sw128((uint32_t)((nt * 16 + b_row) * 128 + ks * 32 + b_kh));
                uint32_t bh[4], bl[4];
                ldsm4(bh, bbase_h + boff);
                ldsm4(bl, bbase_l + boff);
                mma16816(acc[2 * nt],     ah, bh[0], bh[1]);
                mma16816(acc[2 * nt + 1], ah, bh[2], bh[3]);
                mma16816(acc[2 * nt],     ah, bl[0], bl[1]);
                mma16816(acc[2 * nt + 1], ah, bl[2], bl[3]);
                mma16816(acc[2 * nt],     al, bh[0], bh[1]);
                mma16816(acc[2 * nt + 1], al, bh[2], bh[3]);
            }
        }
        __syncthreads();
    }

    // epilogue: thread (grpID, qid) holds rows o = wid*16+grpID(+8), cols j*8 + qid*2 (+1)
    {
        const int grpID = lane >> 2, qid = lane & 3;
        if (LAYER == 0 && wid < 4) {
            #pragma unroll
            for (int half = 0; half < 2; half++) {
                int o = wid * 16 + grpID + half * 8;
                float bo = bias[o];
                #pragma unroll
                for (int j = 0; j < 16; j++) {
                    int c0 = j * 8 + qid * 2;
                    int g = c0 >> 5, d = c0 & 31;
                    float2 v;
                    v.x = fmaxf(acc[j][half * 2 + 0] + bo, 0.f);
                    v.y = fmaxf(acc[j][half * 2 + 1] + bo, 0.f);
                    *(float2*)(g_hid + (size_t)(b0 + g) * 2048 + o * 32 + d) = v;
                }
            }
        } else {
            #pragma unroll
            for (int half = 0; half < 2; half++) {
                int o = wid * 16 + grpID + half * 8;
                float bo = bias[o];
                #pragma unroll
                for (int g = 0; g < 4; g++) {
                    float s = 0.f;
                    #pragma unroll
                    for (int j = 4 * g; j < 4 * g + 4; j++)
                        s += fmaxf(acc[j][half * 2] + bo, 0.f) + fmaxf(acc[j][half * 2 + 1] + bo, 0.f);
                    s += __shfl_xor_sync(0xffffffffu, s, 1);
                    s += __shfl_xor_sync(0xffffffffu, s, 2);
                    if (qid == 0) {
                        if (LAYER == 0) g_ds[(size_t)(b0 + g) * 64 + (o - 64)] = s;
                        else            g_s1[(size_t)(b0 + g) * 128 + o] = s;
                    }
                }
            }
        }
    }
}

// ---------------- linear ----------------
__global__ __launch_bounds__(256)
void lin_kernel(const float* __restrict__ x, const float* __restrict__ lw,
                const float* __restrict__ lb) {
    int warp = threadIdx.x >> 5, lane = threadIdx.x & 31;
    int b = blockIdx.x * 8 + warp;
    const float* xr = x + (size_t)b * 1280;
    float s = 0.f;
    for (int k = lane; k < 1280; k += 32) s += xr[k] * lw[k];
    #pragma unroll
    for (int off = 16; off; off >>= 1) s += __shfl_xor_sync(0xffffffffu, s, off);
    if (lane == 0) g_aux1[b] = s + lb[0];
}

// ---------------- deep layer: out = relu(LN(A @ W^T + bias)) ----------------
template<int N, int ROWS, int TM, int TN, int K>
__global__ __launch_bounds__(256)
void deep_kernel(const float* __restrict__ A, const float* __restrict__ W,
                 const float* __restrict__ bias, const float* __restrict__ gam,
                 const float* __restrict__ bet, float* __restrict__ out) {
    __shared__ float As[16][ROWS];
    __shared__ float Bs[16][N];
    const int tid = threadIdx.x;
    const int tx = tid & 15, ty = tid >> 4;
    const int r0 = blockIdx.x * ROWS;

    float acc[TM][TN];
    #pragma unroll
    for (int i = 0; i < TM; i++)
        #pragma unroll
        for (int j = 0; j < TN; j++) acc[i][j] = 0.f;

    for (int k0 = 0; k0 < K; k0 += 16) {
        for (int i = tid; i < ROWS * 4; i += 256) {
            int r = i >> 2, q = (i & 3) * 4;
            float4 v = *(const float4*)(A + (size_t)(r0 + r) * K + k0 + q);
            As[q + 0][r] = v.x; As[q + 1][r] = v.y;
            As[q + 2][r] = v.z; As[q + 3][r] = v.w;
        }
        for (int i = tid; i < N * 4; i += 256) {
            int n = i >> 2, q = (i & 3) * 4;
            float4 v = *(const float4*)(W + (size_t)n * K + k0 + q);
            Bs[q + 0][n] = v.x; Bs[q + 1][n] = v.y;
            Bs[q + 2][n] = v.z; Bs[q + 3][n] = v.w;
        }
        __syncthreads();
        #pragma unroll 4
        for (int kc = 0; kc < 16; kc++) {
            float a[TM], bv[TN];
            #pragma unroll
            for (int i = 0; i < TM; i++) a[i] = As[kc][ty * TM + i];
            #pragma unroll
            for (int j = 0; j < TN; j++) bv[j] = Bs[kc][tx * TN + j];
            #pragma unroll
            for (int i = 0; i < TM; i++)
                #pragma unroll
                for (int j = 0; j < TN; j++)
                    acc[i][j] = fmaf(a[i], bv[j], acc[i][j]);
        }
        __syncthreads();
    }

    float bx[TN], gx[TN], btx[TN];
    #pragma unroll
    for (int j = 0; j < TN; j++) {
        bx[j] = bias[tx * TN + j]; gx[j] = gam[tx * TN + j]; btx[j] = bet[tx * TN + j];
    }
    #pragma unroll
    for (int i = 0; i < TM; i++) {
        float ps = 0.f, pq = 0.f;
        #pragma unroll
        for (int j = 0; j < TN; j++) {
            float v = acc[i][j] + bx[j];
            acc[i][j] = v; ps += v; pq += v * v;
        }
        #pragma unroll
        for (int off = 8; off; off >>= 1) {
            ps += __shfl_xor_sync(0xffffffffu, ps, off, 16);
            pq += __shfl_xor_sync(0xffffffffu, pq, off, 16);
        }
        float mu = ps * (1.0f / N);
        float var = pq * (1.0f / N) - mu * mu;
        float rs = rsqrtf(var + 1e-5f);
        int r = r0 + ty * TM + i;
        #pragma unroll
        for (int j = 0; j < TN; j++) {
            int n = tx * TN + j;
            float v = (acc[i][j] - mu) * rs * gx[j] + btx[j];
            out[(size_t)r * N + n] = fmaxf(v, 0.f);
        }
    }
}

// ---------------- final aux ----------------
__global__ __launch_bounds__(256)
void aux_final(const float* __restrict__ cw, const float* __restrict__ cb,
               float* __restrict__ out) {
    int warp = threadIdx.x >> 5, lane = threadIdx.x & 31;
    int b = blockIdx.x * 8 + warp;
    float s = 0.f;
    for (int j = lane; j < 64; j += 32)  s += g_ds[(size_t)b * 64 + j]  * cw[j];
    for (int j = lane; j < 128; j += 32) s += g_s1[(size_t)b * 128 + j] * cw[64 + j];
    #pragma unroll
    for (int off = 16; off; off >>= 1) s += __shfl_xor_sync(0xffffffffu, s, off);
    if (lane == 0) out[(size_t)BQ * 64 + b] = g_aux1[b] + s + cb[0];
}

// ---------------- launcher ----------------
extern "C" void kernel_launch(void* const* d_in, const int* in_sizes, int n_in,
                              void* d_out, int out_size) {
    const float* x       = (const float*)d_in[0];
    const float* emb     = (const float*)d_in[1];
    const float* lin_w   = (const float*)d_in[2];
    const float* lin_b   = (const float*)d_in[3];
    const float* conv_w0 = (const float*)d_in[4];
    const float* conv_b0 = (const float*)d_in[5];
    const float* conv_w1 = (const float*)d_in[6];
    const float* conv_b1 = (const float*)d_in[7];
    const float* cow     = (const float*)d_in[8];
    const float* cob     = (const float*)d_in[9];
    const float* dw0     = (const float*)d_in[10];
    const float* db0     = (const float*)d_in[11];
    const float* lg0     = (const float*)d_in[12];
    const float* lb0     = (const float*)d_in[13];
    const float* dw1     = (const float*)d_in[14];
    const float* db1     = (const float*)d_in[15];
    const float* lg1     = (const float*)d_in[16];
    const float* lb1     = (const float*)d_in[17];
    const float* dw2     = (const float*)d_in[18];
    const float* db2     = (const float*)d_in[19];
    const float* lg2     = (const float*)d_in[20];
    const float* lb2     = (const float*)d_in[21];
    float* out = (float*)d_out;

    float *h0, *h1d;
    __nv_bfloat16 *w0h, *w0l, *w1h, *w1l;
    cudaGetSymbolAddress((void**)&h0, g_h0);
    cudaGetSymbolAddress((void**)&h1d, g_h1d);
    cudaGetSymbolAddress((void**)&w0h, g_w0h);
    cudaGetSymbolAddress((void**)&w0l, g_w0l);
    cudaGetSymbolAddress((void**)&w1h, g_w1h);
    cudaGetSymbolAddress((void**)&w1l, g_w1l);

    cudaFuncSetAttribute(cin_mma_kernel<0>, cudaFuncAttributeMaxDynamicSharedMemorySize, 87040);
    cudaFuncSetAttribute(cin_mma_kernel<1>, cudaFuncAttributeMaxDynamicSharedMemorySize, 99328);

    wsplit_kernel<<<(128 * 800 + 255) / 256, 256>>>(conv_w0, w0h, w0l, 1600);
    wsplit_kernel<<<(128 * 1280 + 255) / 256, 256>>>(conv_w1, w1h, w1l, 2560);

    lin_kernel<<<BQ / 8, 256>>>(x, lin_w, lin_b);
    deep_kernel<256, 32, 2, 16, 1280><<<BQ / 32, 256>>>(x, dw0, db0, lg0, lb0, h0);
    deep_kernel<128, 64, 4, 8, 256><<<BQ / 64, 256>>>(h0, dw1, db1, lg1, lb1, h1d);
    deep_kernel<64, 128, 8, 4, 128><<<BQ / 128, 256>>>(h1d, dw2, db2, lg2, lb2, out);

    cin_mma_kernel<0><<<BQ / 4, 256, 87040>>>(emb, w0h, w0l, conv_b0);
    cin_mma_kernel<1><<<BQ / 4, 256, 99328>>>(emb, w1h, w1l, conv_b1);

    aux_final<<<BQ / 8, 256>>>(cow, cob, out);
}

// round 13
// speedup vs baseline: 2.7657x; 1.0164x over previous
#include <cuda_runtime.h>
#include <cuda_bf16.h>
#include <cstdint>

#define BQ 16384

// ---------------- scratch (device globals; no runtime allocation) ----------------
__device__ __align__(16) float g_h0 [BQ * 256];
__device__ __align__(16) float g_h1d[BQ * 128];
__device__ __align__(16) float g_hid[BQ * 64 * 32];
__device__ __align__(16) float g_ds [BQ * 64];
__device__ __align__(16) float g_s1 [BQ * 128];
__device__ __align__(16) float g_aux1[BQ];
// split-bf16 W, stored as pre-swizzled 16KB chunk tiles: [chunk][sw(o*128+kk*2)]
__device__ __align__(16) __nv_bfloat16 g_w0h[128 * 1600];
__device__ __align__(16) __nv_bfloat16 g_w0l[128 * 1600];
__device__ __align__(16) __nv_bfloat16 g_w1h[128 * 2560];
__device__ __align__(16) __nv_bfloat16 g_w1l[128 * 2560];

// ---------------- helpers ----------------
__device__ __forceinline__ uint32_t smem_to_u32(const void* p) {
    uint32_t a;
    asm("{ .reg .u64 t; cvta.to.shared.u64 t, %1; cvt.u32.u64 %0, t; }" : "=r"(a) : "l"(p));
    return a;
}
__device__ __forceinline__ uint32_t sw128(uint32_t off) { return off ^ ((off >> 3) & 0x70); }

__device__ __forceinline__ void ldsm4(uint32_t* r, uint32_t addr) {
    asm volatile("ldmatrix.sync.aligned.m8n8.x4.shared.b16 {%0,%1,%2,%3}, [%4];"
                 : "=r"(r[0]), "=r"(r[1]), "=r"(r[2]), "=r"(r[3]) : "r"(addr));
}
__device__ __forceinline__ void mma16816(float* d, const uint32_t* a, uint32_t b0, uint32_t b1) {
    asm volatile("mma.sync.aligned.m16n8k16.row.col.f32.bf16.bf16.f32 "
                 "{%0,%1,%2,%3}, {%4,%5,%6,%7}, {%8,%9}, {%0,%1,%2,%3};"
                 : "+f"(d[0]), "+f"(d[1]), "+f"(d[2]), "+f"(d[3])
                 : "r"(a[0]), "r"(a[1]), "r"(a[2]), "r"(a[3]), "r"(b0), "r"(b1));
}
__device__ __forceinline__ void cp_async16(uint32_t smem_addr, const void* gptr) {
    asm volatile("cp.async.cg.shared.global [%0], [%1], 16;" :: "r"(smem_addr), "l"(gptr));
}
#define CP_ASYNC_WAIT_ALL() \
    asm volatile("cp.async.commit_group;\ncp.async.wait_group 0;" ::: "memory")

// ---------------- W split+tile precompute ----------------
__global__ __launch_bounds__(256)
void wsplit_kernel(const float* __restrict__ w, __nv_bfloat16* __restrict__ hi,
                   __nv_bfloat16* __restrict__ lo, int K) {
    int t = blockIdx.x * 256 + threadIdx.x;
    int total = 128 * (K >> 1);
    if (t >= total) return;
    int hk = K >> 1;
    int o = t / hk, p = t - o * hk;
    int k = p * 2;
    float v0 = w[o * K + k], v1 = w[o * K + k + 1];
    __nv_bfloat16 h0 = __float2bfloat16(v0), h1 = __float2bfloat16(v1);
    __nv_bfloat16 l0 = __float2bfloat16(v0 - __bfloat162float(h0));
    __nv_bfloat16 l1 = __float2bfloat16(v1 - __bfloat162float(h1));
    int chunk = k >> 6, kk = k & 63;
    uint32_t off = chunk * 16384 + sw128((uint32_t)(o * 128 + kk * 2));
    uint32_t ph = (uint32_t)__bfloat16_as_ushort(h0) | ((uint32_t)__bfloat16_as_ushort(h1) << 16);
    uint32_t pl = (uint32_t)__bfloat16_as_ushort(l0) | ((uint32_t)__bfloat16_as_ushort(l1) << 16);
    *(uint32_t*)((char*)hi + off) = ph;
    *(uint32_t*)((char*)lo + off) = pl;
}

// ---------------- CIN tensor kernel (mma.sync, plain sm_103) ----------------
// LAYER 0: K=1600, k=m*40+n, z = x[m]*x[n] (xs in smem, rotated (d+m)&31)
// LAYER 1: K=2560, k=m*64+n, m==ch per chunk; z = x[g,ch,d]*hid[n,d]
// Warp tile: 32 rows (o) x 64 cols (c): rowgrp=(wid&3), colstrip=(wid>>2).
// Split-bf16 3-pass compensation; single 64KB buffer; cp.async A-fill; 2 CTAs/SM.
template<int LAYER>
__global__ __launch_bounds__(256, 2)
void cin_mma_kernel(const float* __restrict__ emb,
                    const __nv_bfloat16* __restrict__ Wh,
                    const __nv_bfloat16* __restrict__ Wl,
                    const float* __restrict__ bias) {
    constexpr int K   = LAYER ? 2560 : 1600;
    constexpr int NCH = K / 64;
    constexpr int OFF_XS  = 1024;
    constexpr int OFF_HS  = 1024;
    constexpr int OFF_BUF = LAYER ? (1024 + 32768) : (1024 + 20480);

    extern __shared__ char smem[];
    const uint32_t sb = smem_to_u32(smem);
    const int tid = threadIdx.x, wid = tid >> 5, lane = tid & 31;
    const int b0 = blockIdx.x * 4;
    float* xs = (float*)(smem + OFF_XS);
    float* hs = (float*)(smem + OFF_HS);

    if (LAYER == 0) {
        const float* esrc = emb + (size_t)b0 * 1280;
        for (int e = tid; e < 5120; e += 256) {
            int g = e / 1280, r = e - g * 1280, m = r >> 5, d = r & 31;
            xs[g * 1280 + m * 32 + ((d + m) & 31)] = esrc[e];
        }
    } else {
        const float* hsrc = g_hid + (size_t)b0 * 2048;
        for (int e = tid; e < 8192; e += 256) {
            int g = e >> 11, r = e & 2047, n = r >> 5, d = r & 31;
            hs[g * 2048 + n * 32 + ((d + (n >> 1)) & 31)] = hsrc[e];
        }
    }
    __syncthreads();

    // Z-gen assignment: warp w -> g = w>>1, d-block = (w&1)*16; lane -> k-pair (2l,2l+1)
    const int zg = wid >> 1, zdb = (wid & 1) * 16;
    const float* xb = xs + zg * 1280;
    const float* hb = hs + zg * 2048;
    const float* xgl = emb + (size_t)(b0 + zg) * 1280 + zdb;

    // MMA tile assignment: rows rowbase..rowbase+31, cols colbase..colbase+63
    const int rowbase = (wid & 3) * 32;
    const int colbase = (wid >> 2) * 64;

    float acc[2][8][4];
    #pragma unroll
    for (int mt = 0; mt < 2; mt++)
        #pragma unroll
        for (int j = 0; j < 8; j++)
            #pragma unroll
            for (int q = 0; q < 4; q++) acc[mt][j][q] = 0.f;

    const uint32_t a0 = (uint32_t)((rowbase + (lane & 15)) * 128 + (lane >> 4) * 16);
    const int l8 = lane & 7, grp = lane >> 3;
    const uint32_t b_row = (uint32_t)((grp >> 1) * 8 + l8);
    const uint32_t b_kh = (uint32_t)((grp & 1) * 16);

    const uint32_t abase_h = sb + OFF_BUF;
    const uint32_t abase_l = abase_h + 16384;
    const uint32_t bbase_h = abase_h + 32768;
    const uint32_t bbase_l = abase_h + 49152;
    char* Bh = smem + OFF_BUF + 32768;
    char* Bl = smem + OFF_BUF + 49152;

    for (int ch = 0; ch < NCH; ch++) {
        // A-fill: cp.async linear copy of pre-swizzled tiles (hi, lo)
        {
            const char* sh = (const char*)Wh + ch * 16384;
            const char* sl = (const char*)Wl + ch * 16384;
            #pragma unroll
            for (int q = 0; q < 4; q++) {
                int idx = (tid + 256 * q) * 16;
                cp_async16(abase_h + idx, sh + idx);
                cp_async16(abase_l + idx, sl + idx);
            }
        }
        // B-fill: Z chunk split into bf16 hi/lo (overlaps cp.async latency)
        if (LAYER == 0) {
            int k = ch * 64 + lane * 2;
            int m0 = k / 40, n0 = k - m0 * 40;
            int m1 = (k + 1) / 40, n1 = (k + 1) - m1 * 40;
            const int am0 = m0 * 32, an0 = n0 * 32, am1 = m1 * 32, an1 = n1 * 32;
            #pragma unroll
            for (int i = 0; i < 16; i++) {
                int d = zdb + i;
                float z0 = xb[am0 + ((d + m0) & 31)] * xb[an0 + ((d + n0) & 31)];
                float z1 = xb[am1 + ((d + m1) & 31)] * xb[an1 + ((d + n1) & 31)];
                __nv_bfloat16 h0 = __float2bfloat16(z0), h1 = __float2bfloat16(z1);
                __nv_bfloat16 l0 = __float2bfloat16(z0 - __bfloat162float(h0));
                __nv_bfloat16 l1 = __float2bfloat16(z1 - __bfloat162float(h1));
                uint32_t phv = (uint32_t)__bfloat16_as_ushort(h0) | ((uint32_t)__bfloat16_as_ushort(h1) << 16);
                uint32_t plv = (uint32_t)__bfloat16_as_ushort(l0) | ((uint32_t)__bfloat16_as_ushort(l1) << 16);
                uint32_t off = sw128((uint32_t)((wid * 16 + i) * 128 + lane * 4));
                *(uint32_t*)(Bh + off) = phv;
                *(uint32_t*)(Bl + off) = plv;
            }
        } else {
            float xv[16];
            const float4* xr = (const float4*)(xgl + ch * 32);
            #pragma unroll
            for (int q = 0; q < 4; q++) {
                float4 v = xr[q];
                xv[4 * q + 0] = v.x; xv[4 * q + 1] = v.y;
                xv[4 * q + 2] = v.z; xv[4 * q + 3] = v.w;
            }
            const int n0 = lane * 2, n1 = n0 + 1;
            const float* h0p = hb + n0 * 32;
            const float* h1p = hb + n1 * 32;
            #pragma unroll
            for (int i = 0; i < 16; i++) {
                int d = zdb + i;
                int rot = (d + lane) & 31;
                float z0 = xv[i] * h0p[rot];
                float z1 = xv[i] * h1p[rot];
                __nv_bfloat16 h0 = __float2bfloat16(z0), h1 = __float2bfloat16(z1);
                __nv_bfloat16 l0 = __float2bfloat16(z0 - __bfloat162float(h0));
                __nv_bfloat16 l1 = __float2bfloat16(z1 - __bfloat162float(h1));
                uint32_t phv = (uint32_t)__bfloat16_as_ushort(h0) | ((uint32_t)__bfloat16_as_ushort(h1) << 16);
                uint32_t plv = (uint32_t)__bfloat16_as_ushort(l0) | ((uint32_t)__bfloat16_as_ushort(l1) << 16);
                uint32_t off = sw128((uint32_t)((wid * 16 + i) * 128 + lane * 4));
                *(uint32_t*)(Bh + off) = phv;
                *(uint32_t*)(Bl + off) = plv;
            }
        }
        CP_ASYNC_WAIT_ALL();
        __syncthreads();

        #pragma unroll
        for (int ks = 0; ks < 4; ks++) {
            uint32_t ah[2][4], al[2][4];
            #pragma unroll
            for (int mt = 0; mt < 2; mt++) {
                uint32_t aoff = sw128(a0 + mt * 2048 + ks * 32);
                ldsm4(ah[mt], abase_h + aoff);
                ldsm4(al[mt], abase_l + aoff);
            }
            #pragma unroll
            for (int nt = 0; nt < 4; nt++) {
                uint32_t boff = sw128((uint32_t)((colbase + nt * 16 + b_row) * 128 + ks * 32 + b_kh));
                uint32_t bh[4], bl[4];
                ldsm4(bh, bbase_h + boff);
                ldsm4(bl, bbase_l + boff);
                #pragma unroll
                for (int mt = 0; mt < 2; mt++) {
                    mma16816(acc[mt][2 * nt],     ah[mt], bh[0], bh[1]);
                    mma16816(acc[mt][2 * nt + 1], ah[mt], bh[2], bh[3]);
                    mma16816(acc[mt][2 * nt],     ah[mt], bl[0], bl[1]);
                    mma16816(acc[mt][2 * nt + 1], ah[mt], bl[2], bl[3]);
                    mma16816(acc[mt][2 * nt],     al[mt], bh[0], bh[1]);
                    mma16816(acc[mt][2 * nt + 1], al[mt], bh[2], bh[3]);
                }
            }
        }
        __syncthreads();
    }

    // epilogue: thread (grpID, qid); row o = rowbase + mt*16 + grpID + half*8,
    // col c = colbase + nt8*8 + qid*2 (+1)
    {
        const int grpID = lane >> 2, qid = lane & 3;
        if (LAYER == 0 && rowbase < 64) {
            #pragma unroll
            for (int mt = 0; mt < 2; mt++) {
                #pragma unroll
                for (int half = 0; half < 2; half++) {
                    int o = rowbase + mt * 16 + grpID + half * 8;
                    float bo = bias[o];
                    #pragma unroll
                    for (int nt8 = 0; nt8 < 8; nt8++) {
                        int c = colbase + nt8 * 8 + qid * 2;
                        int g = c >> 5, d = c & 31;
                        float2 v;
                        v.x = fmaxf(acc[mt][nt8][half * 2 + 0] + bo, 0.f);
                        v.y = fmaxf(acc[mt][nt8][half * 2 + 1] + bo, 0.f);
                        *(float2*)(g_hid + (size_t)(b0 + g) * 2048 + o * 32 + d) = v;
                    }
                }
            }
        } else {
            #pragma unroll
            for (int mt = 0; mt < 2; mt++) {
                #pragma unroll
                for (int half = 0; half < 2; half++) {
                    int o = rowbase + mt * 16 + grpID + half * 8;
                    float bo = bias[o];
                    #pragma unroll
                    for (int gg = 0; gg < 2; gg++) {
                        float s = 0.f;
                        #pragma unroll
                        for (int nt8 = 4 * gg; nt8 < 4 * gg + 4; nt8++)
                            s += fmaxf(acc[mt][nt8][half * 2] + bo, 0.f)
                               + fmaxf(acc[mt][nt8][half * 2 + 1] + bo, 0.f);
                        s += __shfl_xor_sync(0xffffffffu, s, 1);
                        s += __shfl_xor_sync(0xffffffffu, s, 2);
                        if (qid == 0) {
                            int g = (colbase >> 5) + gg;
                            if (LAYER == 0) g_ds[(size_t)(b0 + g) * 64 + (o - 64)] = s;
                            else            g_s1[(size_t)(b0 + g) * 128 + o] = s;
                        }
                    }
                }
            }
        }
    }
}

// ---------------- linear ----------------
__global__ __launch_bounds__(256)
void lin_kernel(const float* __restrict__ x, const float* __restrict__ lw,
                const float* __restrict__ lb) {
    int warp = threadIdx.x >> 5, lane = threadIdx.x & 31;
    int b = blockIdx.x * 8 + warp;
    const float* xr = x + (size_t)b * 1280;
    float s = 0.f;
    for (int k = lane; k < 1280; k += 32) s += xr[k] * lw[k];
    #pragma unroll
    for (int off = 16; off; off >>= 1) s += __shfl_xor_sync(0xffffffffu, s, off);
    if (lane == 0) g_aux1[b] = s + lb[0];
}

// ---------------- deep layer: out = relu(LN(A @ W^T + bias)) ----------------
template<int N, int ROWS, int TM, int TN, int K>
__global__ __launch_bounds__(256)
void deep_kernel(const float* __restrict__ A, const float* __restrict__ W,
                 const float* __restrict__ bias, const float* __restrict__ gam,
                 const float* __restrict__ bet, float* __restrict__ out) {
    __shared__ float As[16][ROWS];
    __shared__ float Bs[16][N];
    const int tid = threadIdx.x;
    const int tx = tid & 15, ty = tid >> 4;
    const int r0 = blockIdx.x * ROWS;

    float acc[TM][TN];
    #pragma unroll
    for (int i = 0; i < TM; i++)
        #pragma unroll
        for (int j = 0; j < TN; j++) acc[i][j] = 0.f;

    for (int k0 = 0; k0 < K; k0 += 16) {
        for (int i = tid; i < ROWS * 4; i += 256) {
            int r = i >> 2, q = (i & 3) * 4;
            float4 v = *(const float4*)(A + (size_t)(r0 + r) * K + k0 + q);
            As[q + 0][r] = v.x; As[q + 1][r] = v.y;
            As[q + 2][r] = v.z; As[q + 3][r] = v.w;
        }
        for (int i = tid; i < N * 4; i += 256) {
            int n = i >> 2, q = (i & 3) * 4;
            float4 v = *(const float4*)(W + (size_t)n * K + k0 + q);
            Bs[q + 0][n] = v.x; Bs[q + 1][n] = v.y;
            Bs[q + 2][n] = v.z; Bs[q + 3][n] = v.w;
        }
        __syncthreads();
        #pragma unroll 4
        for (int kc = 0; kc < 16; kc++) {
            float a[TM], bv[TN];
            #pragma unroll
            for (int i = 0; i < TM; i++) a[i] = As[kc][ty * TM + i];
            #pragma unroll
            for (int j = 0; j < TN; j++) bv[j] = Bs[kc][tx * TN + j];
            #pragma unroll
            for (int i = 0; i < TM; i++)
                #pragma unroll
                for (int j = 0; j < TN; j++)
                    acc[i][j] = fmaf(a[i], bv[j], acc[i][j]);
        }
        __syncthreads();
    }

    float bx[TN], gx[TN], btx[TN];
    #pragma unroll
    for (int j = 0; j < TN; j++) {
        bx[j] = bias[tx * TN + j]; gx[j] = gam[tx * TN + j]; btx[j] = bet[tx * TN + j];
    }
    #pragma unroll
    for (int i = 0; i < TM; i++) {
        float ps = 0.f, pq = 0.f;
        #pragma unroll
        for (int j = 0; j < TN; j++) {
            float v = acc[i][j] + bx[j];
            acc[i][j] = v; ps += v; pq += v * v;
        }
        #pragma unroll
        for (int off = 8; off; off >>= 1) {
            ps += __shfl_xor_sync(0xffffffffu, ps, off, 16);
            pq += __shfl_xor_sync(0xffffffffu, pq, off, 16);
        }
        float mu = ps * (1.0f / N);
        float var = pq * (1.0f / N) - mu * mu;
        float rs = rsqrtf(var + 1e-5f);
        int r = r0 + ty * TM + i;
        #pragma unroll
        for (int j = 0; j < TN; j++) {
            int n = tx * TN + j;
            float v = (acc[i][j] - mu) * rs * gx[j] + btx[j];
            out[(size_t)r * N + n] = fmaxf(v, 0.f);
        }
    }
}

// ---------------- final aux ----------------
__global__ __launch_bounds__(256)
void aux_final(const float* __restrict__ cw, const float* __restrict__ cb,
               float* __restrict__ out) {
    int warp = threadIdx.x >> 5, lane = threadIdx.x & 31;
    int b = blockIdx.x * 8 + warp;
    float s = 0.f;
    for (int j = lane; j < 64; j += 32)  s += g_ds[(size_t)b * 64 + j]  * cw[j];
    for (int j = lane; j < 128; j += 32) s += g_s1[(size_t)b * 128 + j] * cw[64 + j];
    #pragma unroll
    for (int off = 16; off; off >>= 1) s += __shfl_xor_sync(0xffffffffu, s, off);
    if (lane == 0) out[(size_t)BQ * 64 + b] = g_aux1[b] + s + cb[0];
}

// ---------------- launcher ----------------
extern "C" void kernel_launch(void* const* d_in, const int* in_sizes, int n_in,
                              void* d_out, int out_size) {
    const float* x       = (const float*)d_in[0];
    const float* emb     = (const float*)d_in[1];
    const float* lin_w   = (const float*)d_in[2];
    const float* lin_b   = (const float*)d_in[3];
    const float* conv_w0 = (const float*)d_in[4];
    const float* conv_b0 = (const float*)d_in[5];
    const float* conv_w1 = (const float*)d_in[6];
    const float* conv_b1 = (const float*)d_in[7];
    const float* cow     = (const float*)d_in[8];
    const float* cob     = (const float*)d_in[9];
    const float* dw0     = (const float*)d_in[10];
    const float* db0     = (const float*)d_in[11];
    const float* lg0     = (const float*)d_in[12];
    const float* lb0     = (const float*)d_in[13];
    const float* dw1     = (const float*)d_in[14];
    const float* db1     = (const float*)d_in[15];
    const float* lg1     = (const float*)d_in[16];
    const float* lb1     = (const float*)d_in[17];
    const float* dw2     = (const float*)d_in[18];
    const float* db2     = (const float*)d_in[19];
    const float* lg2     = (const float*)d_in[20];
    const float* lb2     = (const float*)d_in[21];
    float* out = (float*)d_out;

    float *h0, *h1d;
    __nv_bfloat16 *w0h, *w0l, *w1h, *w1l;
    cudaGetSymbolAddress((void**)&h0, g_h0);
    cudaGetSymbolAddress((void**)&h1d, g_h1d);
    cudaGetSymbolAddress((void**)&w0h, g_w0h);
    cudaGetSymbolAddress((void**)&w0l, g_w0l);
    cudaGetSymbolAddress((void**)&w1h, g_w1h);
    cudaGetSymbolAddress((void**)&w1l, g_w1l);

    cudaFuncSetAttribute(cin_mma_kernel<0>, cudaFuncAttributeMaxDynamicSharedMemorySize, 87040);
    cudaFuncSetAttribute(cin_mma_kernel<1>, cudaFuncAttributeMaxDynamicSharedMemorySize, 99328);

    wsplit_kernel<<<(128 * 800 + 255) / 256, 256>>>(conv_w0, w0h, w0l, 1600);
    wsplit_kernel<<<(128 * 1280 + 255) / 256, 256>>>(conv_w1, w1h, w1l, 2560);

    lin_kernel<<<BQ / 8, 256>>>(x, lin_w, lin_b);
    deep_kernel<256, 32, 2, 16, 1280><<<BQ / 32, 256>>>(x, dw0, db0, lg0, lb0, h0);
    deep_kernel<128, 64, 4, 8, 256><<<BQ / 64, 256>>>(h0, dw1, db1, lg1, lb1, h1d);
    deep_kernel<64, 128, 8, 4, 128><<<BQ / 128, 256>>>(h1d, dw2, db2, lg2, lb2, out);

    cin_mma_kernel<0><<<BQ / 4, 256, 87040>>>(emb, w0h, w0l, conv_b0);
    cin_mma_kernel<1><<<BQ / 4, 256, 99328>>>(emb, w1h, w1l, conv_b1);

    aux_final<<<BQ / 8, 256>>>(cow, cob, out);
}

// round 14
// speedup vs baseline: 3.6119x; 1.3060x over previous
#include <cuda_runtime.h>
#include <cuda_fp16.h>
#include <cstdint>

#define BQ 16384

// ---------------- scratch (device globals; no runtime allocation) ----------------
__device__ __align__(16) float g_h0 [BQ * 256];
__device__ __align__(16) float g_h1d[BQ * 128];
__device__ __align__(16) float g_hid[BQ * 64 * 32];
__device__ __align__(16) float g_ds [BQ * 64];
__device__ __align__(16) float g_s1 [BQ * 128];
__device__ __align__(16) float g_aux1[BQ];
// fp16 W tiles, pre-swizzled 16KB chunks: [chunk][sw(o*128 + kk*2)]
// L0 is symmetrized upper-triangle: K = 820 pairs padded to 832 (13 chunks)
__device__ __align__(16) __half g_w0f[13 * 8192];
__device__ __align__(16) __half g_w1f[40 * 8192];

// ---------------- helpers ----------------
__device__ __forceinline__ uint32_t smem_to_u32(const void* p) {
    uint32_t a;
    asm("{ .reg .u64 t; cvta.to.shared.u64 t, %1; cvt.u32.u64 %0, t; }" : "=r"(a) : "l"(p));
    return a;
}
__device__ __forceinline__ uint32_t sw128(uint32_t off) { return off ^ ((off >> 3) & 0x70); }

__device__ __forceinline__ void ldsm4(uint32_t* r, uint32_t addr) {
    asm volatile("ldmatrix.sync.aligned.m8n8.x4.shared.b16 {%0,%1,%2,%3}, [%4];"
                 : "=r"(r[0]), "=r"(r[1]), "=r"(r[2]), "=r"(r[3]) : "r"(addr));
}
__device__ __forceinline__ void mma16816f(float* d, const uint32_t* a, uint32_t b0, uint32_t b1) {
    asm volatile("mma.sync.aligned.m16n8k16.row.col.f32.f16.f16.f32 "
                 "{%0,%1,%2,%3}, {%4,%5,%6,%7}, {%8,%9}, {%0,%1,%2,%3};"
                 : "+f"(d[0]), "+f"(d[1]), "+f"(d[2]), "+f"(d[3])
                 : "r"(a[0]), "r"(a[1]), "r"(a[2]), "r"(a[3]), "r"(b0), "r"(b1));
}
__device__ __forceinline__ void cp_async16(uint32_t smem_addr, const void* gptr) {
    asm volatile("cp.async.cg.shared.global [%0], [%1], 16;" :: "r"(smem_addr), "l"(gptr));
}
#define CP_ASYNC_WAIT_ALL() \
    asm volatile("cp.async.commit_group;\ncp.async.wait_group 0;" ::: "memory")

// ---------------- W prep: L0 symmetrized triangle, fp16, pre-swizzled ----------------
__global__ __launch_bounds__(256)
void wprep0_kernel(const float* __restrict__ w, __half* __restrict__ dst) {
    int t = blockIdx.x * 256 + threadIdx.x;   // 128 * 832 = 106496 exactly
    int o = t / 832, p = t - o * 832;
    float v = 0.f;
    if (p < 820) {
        int pp = p, m = 0;
        while (pp >= 40 - m) { pp -= 40 - m; m++; }
        int n = m + pp;
        v = w[o * 1600 + m * 40 + n];
        if (n > m) v += w[o * 1600 + n * 40 + m];
    }
    int chunk = p >> 6, kk = p & 63;
    uint32_t off = chunk * 16384 + sw128((uint32_t)(o * 128 + kk * 2));
    *(__half*)((char*)dst + off) = __float2half(v);
}

__global__ __launch_bounds__(256)
void wprep1_kernel(const float* __restrict__ w, __half* __restrict__ dst) {
    int t = blockIdx.x * 256 + threadIdx.x;   // 128 * 2560 = 327680 exactly
    int o = t / 2560, k = t - o * 2560;
    float v = w[o * 2560 + k];
    int chunk = k >> 6, kk = k & 63;
    uint32_t off = chunk * 16384 + sw128((uint32_t)(o * 128 + kk * 2));
    *(__half*)((char*)dst + off) = __float2half(v);
}

// ---------------- CIN tensor kernel (fp16 mma.sync, 2-pass z-split) ----------------
// LAYER 0: K=832 triangle pairs (m<=n), z = x[m]*x[n], W symmetrized.
// LAYER 1: K=2560, k=m*64+n, m==ch per chunk; z = x[g,ch,d]*hid[n,d].
// W single fp16 (A, 16KB/chunk); Z split fp16 hi/lo (B, 2x16KB); 2 MMA passes.
// Warp tile 32(o) x 64(c). cp.async A-fill. 2 CTAs/SM.
template<int LAYER>
__global__ __launch_bounds__(256, 2)
void cin_mma_kernel(const float* __restrict__ emb,
                    const __half* __restrict__ Wf,
                    const float* __restrict__ bias) {
    constexpr int NCH     = LAYER ? 40 : 13;
    constexpr int OFF_XS  = LAYER ? 1024 : 2048;   // L0 reserves [0,2048) for tri LUT
    constexpr int OFF_BUF = LAYER ? (1024 + 32768) : (2048 + 20480);

    extern __shared__ char smem[];
    const uint32_t sb = smem_to_u32(smem);
    const int tid = threadIdx.x, wid = tid >> 5, lane = tid & 31;
    const int b0 = blockIdx.x * 4;
    float* xs = (float*)(smem + OFF_XS);
    float* hs = (float*)(smem + OFF_XS);
    uint16_t* tri = (uint16_t*)smem;

    if (LAYER == 0) {
        // triangle LUT: p -> (m<<8)|n ; 0xFFFF for pad
        for (int p = tid; p < 832; p += 256) {
            uint16_t val = 0xFFFFu;
            if (p < 820) {
                int pp = p, m = 0;
                while (pp >= 40 - m) { pp -= 40 - m; m++; }
                val = (uint16_t)((m << 8) | (m + pp));
            }
            tri[p] = val;
        }
        // x rotated: (g,m,d) at xs[g*1280 + m*32 + ((d+m)&31)]
        const float* esrc = emb + (size_t)b0 * 1280;
        for (int e = tid; e < 5120; e += 256) {
            int g = e / 1280, r = e - g * 1280, m = r >> 5, d = r & 31;
            xs[g * 1280 + m * 32 + ((d + m) & 31)] = esrc[e];
        }
    } else {
        // hid rotated: (g,n,d) at hs[g*2048 + n*32 + ((d+(n>>1))&31)]
        const float* hsrc = g_hid + (size_t)b0 * 2048;
        for (int e = tid; e < 8192; e += 256) {
            int g = e >> 11, r = e & 2047, n = r >> 5, d = r & 31;
            hs[g * 2048 + n * 32 + ((d + (n >> 1)) & 31)] = hsrc[e];
        }
    }
    __syncthreads();

    // Z-gen assignment: warp w -> g = w>>1, d-block = (w&1)*16; lane -> k-pair (2l,2l+1)
    const int zg = wid >> 1, zdb = (wid & 1) * 16;
    const float* xb = xs + zg * 1280;
    const float* hb = hs + zg * 2048;
    const float* xgl = emb + (size_t)(b0 + zg) * 1280 + zdb;

    // MMA tile assignment: rows rowbase..+31, cols colbase..+63
    const int rowbase = (wid & 3) * 32;
    const int colbase = (wid >> 2) * 64;

    float acc[2][8][4];
    #pragma unroll
    for (int mt = 0; mt < 2; mt++)
        #pragma unroll
        for (int j = 0; j < 8; j++)
            #pragma unroll
            for (int q = 0; q < 4; q++) acc[mt][j][q] = 0.f;

    const uint32_t a0 = (uint32_t)((rowbase + (lane & 15)) * 128 + (lane >> 4) * 16);
    const int l8 = lane & 7, grp = lane >> 3;
    const uint32_t b_row = (uint32_t)((grp >> 1) * 8 + l8);
    const uint32_t b_kh = (uint32_t)((grp & 1) * 16);

    const uint32_t abase   = sb + OFF_BUF;
    const uint32_t bbase_h = abase + 16384;
    const uint32_t bbase_l = abase + 32768;
    char* Bh = smem + OFF_BUF + 16384;
    char* Bl = smem + OFF_BUF + 32768;

    for (int ch = 0; ch < NCH; ch++) {
        // A-fill: cp.async linear copy of pre-swizzled fp16 tile (16KB)
        {
            const char* sa = (const char*)Wf + ch * 16384;
            #pragma unroll
            for (int q = 0; q < 4; q++) {
                int idx = (tid + 256 * q) * 16;
                cp_async16(abase + idx, sa + idx);
            }
        }
        // B-fill: Z chunk split into fp16 hi/lo (overlaps cp.async latency)
        if (LAYER == 0) {
            int k = ch * 64 + lane * 2;
            uint32_t t0 = tri[k], t1 = tri[k + 1];
            bool v0 = (t0 != 0xFFFFu), v1 = (t1 != 0xFFFFu);
            int m0 = v0 ? (int)(t0 >> 8) : 0, n0 = v0 ? (int)(t0 & 255) : 0;
            int m1 = v1 ? (int)(t1 >> 8) : 0, n1 = v1 ? (int)(t1 & 255) : 0;
            const int am0 = m0 * 32, an0 = n0 * 32, am1 = m1 * 32, an1 = n1 * 32;
            #pragma unroll
            for (int i = 0; i < 16; i++) {
                int d = zdb + i;
                float z0 = v0 ? xb[am0 + ((d + m0) & 31)] * xb[an0 + ((d + n0) & 31)] : 0.f;
                float z1 = v1 ? xb[am1 + ((d + m1) & 31)] * xb[an1 + ((d + n1) & 31)] : 0.f;
                __half h0 = __float2half(z0), h1 = __float2half(z1);
                __half l0 = __float2half(z0 - __half2float(h0));
                __half l1 = __float2half(z1 - __half2float(h1));
                uint32_t phv = (uint32_t)__half_as_ushort(h0) | ((uint32_t)__half_as_ushort(h1) << 16);
                uint32_t plv = (uint32_t)__half_as_ushort(l0) | ((uint32_t)__half_as_ushort(l1) << 16);
                uint32_t off = sw128((uint32_t)((wid * 16 + i) * 128 + lane * 4));
                *(uint32_t*)(Bh + off) = phv;
                *(uint32_t*)(Bl + off) = plv;
            }
        } else {
            float xv[16];
            const float4* xr = (const float4*)(xgl + ch * 32);
            #pragma unroll
            for (int q = 0; q < 4; q++) {
                float4 v = xr[q];
                xv[4 * q + 0] = v.x; xv[4 * q + 1] = v.y;
                xv[4 * q + 2] = v.z; xv[4 * q + 3] = v.w;
            }
            const int n0 = lane * 2, n1 = n0 + 1;
            const float* h0p = hb + n0 * 32;
            const float* h1p = hb + n1 * 32;
            #pragma unroll
            for (int i = 0; i < 16; i++) {
                int d = zdb + i;
                int rot = (d + lane) & 31;
                float z0 = xv[i] * h0p[rot];
                float z1 = xv[i] * h1p[rot];
                __half h0 = __float2half(z0), h1 = __float2half(z1);
                __half l0 = __float2half(z0 - __half2float(h0));
                __half l1 = __float2half(z1 - __half2float(h1));
                uint32_t phv = (uint32_t)__half_as_ushort(h0) | ((uint32_t)__half_as_ushort(h1) << 16);
                uint32_t plv = (uint32_t)__half_as_ushort(l0) | ((uint32_t)__half_as_ushort(l1) << 16);
                uint32_t off = sw128((uint32_t)((wid * 16 + i) * 128 + lane * 4));
                *(uint32_t*)(Bh + off) = phv;
                *(uint32_t*)(Bl + off) = plv;
            }
        }
        CP_ASYNC_WAIT_ALL();
        __syncthreads();

        #pragma unroll
        for (int ks = 0; ks < 4; ks++) {
            uint32_t a[2][4];
            #pragma unroll
            for (int mt = 0; mt < 2; mt++)
                ldsm4(a[mt], abase + sw128(a0 + mt * 2048 + ks * 32));
            #pragma unroll
            for (int nt = 0; nt < 4; nt++) {
                uint32_t boff = sw128((uint32_t)((colbase + nt * 16 + b_row) * 128 + ks * 32 + b_kh));
                uint32_t bh[4], bl[4];
                ldsm4(bh, bbase_h + boff);
                ldsm4(bl, bbase_l + boff);
                #pragma unroll
                for (int mt = 0; mt < 2; mt++) {
                    mma16816f(acc[mt][2 * nt],     a[mt], bh[0], bh[1]);
                    mma16816f(acc[mt][2 * nt + 1], a[mt], bh[2], bh[3]);
                    mma16816f(acc[mt][2 * nt],     a[mt], bl[0], bl[1]);
                    mma16816f(acc[mt][2 * nt + 1], a[mt], bl[2], bl[3]);
                }
            }
        }
        __syncthreads();
    }

    // epilogue: thread (grpID, qid); row o = rowbase + mt*16 + grpID + half*8,
    // col c = colbase + nt8*8 + qid*2 (+1)
    {
        const int grpID = lane >> 2, qid = lane & 3;
        if (LAYER == 0 && rowbase < 64) {
            #pragma unroll
            for (int mt = 0; mt < 2; mt++) {
                #pragma unroll
                for (int half = 0; half < 2; half++) {
                    int o = rowbase + mt * 16 + grpID + half * 8;
                    float bo = bias[o];
                    #pragma unroll
                    for (int nt8 = 0; nt8 < 8; nt8++) {
                        int c = colbase + nt8 * 8 + qid * 2;
                        int g = c >> 5, d = c & 31;
                        float2 v;
                        v.x = fmaxf(acc[mt][nt8][half * 2 + 0] + bo, 0.f);
                        v.y = fmaxf(acc[mt][nt8][half * 2 + 1] + bo, 0.f);
                        *(float2*)(g_hid + (size_t)(b0 + g) * 2048 + o * 32 + d) = v;
                    }
                }
            }
        } else {
            #pragma unroll
            for (int mt = 0; mt < 2; mt++) {
                #pragma unroll
                for (int half = 0; half < 2; half++) {
                    int o = rowbase + mt * 16 + grpID + half * 8;
                    float bo = bias[o];
                    #pragma unroll
                    for (int gg = 0; gg < 2; gg++) {
                        float s = 0.f;
                        #pragma unroll
                        for (int nt8 = 4 * gg; nt8 < 4 * gg + 4; nt8++)
                            s += fmaxf(acc[mt][nt8][half * 2] + bo, 0.f)
                               + fmaxf(acc[mt][nt8][half * 2 + 1] + bo, 0.f);
                        s += __shfl_xor_sync(0xffffffffu, s, 1);
                        s += __shfl_xor_sync(0xffffffffu, s, 2);
                        if (qid == 0) {
                            int g = (colbase >> 5) + gg;
                            if (LAYER == 0) g_ds[(size_t)(b0 + g) * 64 + (o - 64)] = s;
                            else            g_s1[(size_t)(b0 + g) * 128 + o] = s;
                        }
                    }
                }
            }
        }
    }
}

// ---------------- linear ----------------
__global__ __launch_bounds__(256)
void lin_kernel(const float* __restrict__ x, const float* __restrict__ lw,
                const float* __restrict__ lb) {
    int warp = threadIdx.x >> 5, lane = threadIdx.x & 31;
    int b = blockIdx.x * 8 + warp;
    const float* xr = x + (size_t)b * 1280;
    float s = 0.f;
    for (int k = lane; k < 1280; k += 32) s += xr[k] * lw[k];
    #pragma unroll
    for (int off = 16; off; off >>= 1) s += __shfl_xor_sync(0xffffffffu, s, off);
    if (lane == 0) g_aux1[b] = s + lb[0];
}

// ---------------- deep layer: out = relu(LN(A @ W^T + bias)) ----------------
template<int N, int ROWS, int TM, int TN, int K>
__global__ __launch_bounds__(256)
void deep_kernel(const float* __restrict__ A, const float* __restrict__ W,
                 const float* __restrict__ bias, const float* __restrict__ gam,
                 const float* __restrict__ bet, float* __restrict__ out) {
    __shared__ float As[16][ROWS];
    __shared__ float Bs[16][N];
    const int tid = threadIdx.x;
    const int tx = tid & 15, ty = tid >> 4;
    const int r0 = blockIdx.x * ROWS;

    float acc[TM][TN];
    #pragma unroll
    for (int i = 0; i < TM; i++)
        #pragma unroll
        for (int j = 0; j < TN; j++) acc[i][j] = 0.f;

    for (int k0 = 0; k0 < K; k0 += 16) {
        for (int i = tid; i < ROWS * 4; i += 256) {
            int r = i >> 2, q = (i & 3) * 4;
            float4 v = *(const float4*)(A + (size_t)(r0 + r) * K + k0 + q);
            As[q + 0][r] = v.x; As[q + 1][r] = v.y;
            As[q + 2][r] = v.z; As[q + 3][r] = v.w;
        }
        for (int i = tid; i < N * 4; i += 256) {
            int n = i >> 2, q = (i & 3) * 4;
            float4 v = *(const float4*)(W + (size_t)n * K + k0 + q);
            Bs[q + 0][n] = v.x; Bs[q + 1][n] = v.y;
            Bs[q + 2][n] = v.z; Bs[q + 3][n] = v.w;
        }
        __syncthreads();
        #pragma unroll 4
        for (int kc = 0; kc < 16; kc++) {
            float a[TM], bv[TN];
            #pragma unroll
            for (int i = 0; i < TM; i++) a[i] = As[kc][ty * TM + i];
            #pragma unroll
            for (int j = 0; j < TN; j++) bv[j] = Bs[kc][tx * TN + j];
            #pragma unroll
            for (int i = 0; i < TM; i++)
                #pragma unroll
                for (int j = 0; j < TN; j++)
                    acc[i][j] = fmaf(a[i], bv[j], acc[i][j]);
        }
        __syncthreads();
    }

    float bx[TN], gx[TN], btx[TN];
    #pragma unroll
    for (int j = 0; j < TN; j++) {
        bx[j] = bias[tx * TN + j]; gx[j] = gam[tx * TN + j]; btx[j] = bet[tx * TN + j];
    }
    #pragma unroll
    for (int i = 0; i < TM; i++) {
        float ps = 0.f, pq = 0.f;
        #pragma unroll
        for (int j = 0; j < TN; j++) {
            float v = acc[i][j] + bx[j];
            acc[i][j] = v; ps += v; pq += v * v;
        }
        #pragma unroll
        for (int off = 8; off; off >>= 1) {
            ps += __shfl_xor_sync(0xffffffffu, ps, off, 16);
            pq += __shfl_xor_sync(0xffffffffu, pq, off, 16);
        }
        float mu = ps * (1.0f / N);
        float var = pq * (1.0f / N) - mu * mu;
        float rs = rsqrtf(var + 1e-5f);
        int r = r0 + ty * TM + i;
        #pragma unroll
        for (int j = 0; j < TN; j++) {
            int n = tx * TN + j;
            float v = (acc[i][j] - mu) * rs * gx[j] + btx[j];
            out[(size_t)r * N + n] = fmaxf(v, 0.f);
        }
    }
}

// ---------------- final aux ----------------
__global__ __launch_bounds__(256)
void aux_final(const float* __restrict__ cw, const float* __restrict__ cb,
               float* __restrict__ out) {
    int warp = threadIdx.x >> 5, lane = threadIdx.x & 31;
    int b = blockIdx.x * 8 + warp;
    float s = 0.f;
    for (int j = lane; j < 64; j += 32)  s += g_ds[(size_t)b * 64 + j]  * cw[j];
    for (int j = lane; j < 128; j += 32) s += g_s1[(size_t)b * 128 + j] * cw[64 + j];
    #pragma unroll
    for (int off = 16; off; off >>= 1) s += __shfl_xor_sync(0xffffffffu, s, off);
    if (lane == 0) out[(size_t)BQ * 64 + b] = g_aux1[b] + s + cb[0];
}

// ---------------- launcher ----------------
extern "C" void kernel_launch(void* const* d_in, const int* in_sizes, int n_in,
                              void* d_out, int out_size) {
    const float* x       = (const float*)d_in[0];
    const float* emb     = (const float*)d_in[1];
    const float* lin_w   = (const float*)d_in[2];
    const float* lin_b   = (const float*)d_in[3];
    const float* conv_w0 = (const float*)d_in[4];
    const float* conv_b0 = (const float*)d_in[5];
    const float* conv_w1 = (const float*)d_in[6];
    const float* conv_b1 = (const float*)d_in[7];
    const float* cow     = (const float*)d_in[8];
    const float* cob     = (const float*)d_in[9];
    const float* dw0     = (const float*)d_in[10];
    const float* db0     = (const float*)d_in[11];
    const float* lg0     = (const float*)d_in[12];
    const float* lb0     = (const float*)d_in[13];
    const float* dw1     = (const float*)d_in[14];
    const float* db1     = (const float*)d_in[15];
    const float* lg1     = (const float*)d_in[16];
    const float* lb1     = (const float*)d_in[17];
    const float* dw2     = (const float*)d_in[18];
    const float* db2     = (const float*)d_in[19];
    const float* lg2     = (const float*)d_in[20];
    const float* lb2     = (const float*)d_in[21];
    float* out = (float*)d_out;

    float *h0, *h1d;
    __half *w0f, *w1f;
    cudaGetSymbolAddress((void**)&h0, g_h0);
    cudaGetSymbolAddress((void**)&h1d, g_h1d);
    cudaGetSymbolAddress((void**)&w0f, g_w0f);
    cudaGetSymbolAddress((void**)&w1f, g_w1f);

    cudaFuncSetAttribute(cin_mma_kernel<0>, cudaFuncAttributeMaxDynamicSharedMemorySize, 71680);
    cudaFuncSetAttribute(cin_mma_kernel<1>, cudaFuncAttributeMaxDynamicSharedMemorySize, 82944);

    // order chosen so ncu's fixed skip-count lands on a CIN kernel
    wprep0_kernel<<<416, 256>>>(conv_w0, w0f);
    wprep1_kernel<<<1280, 256>>>(conv_w1, w1f);
    cin_mma_kernel<0><<<BQ / 4, 256, 71680>>>(emb, w0f, conv_b0);
    cin_mma_kernel<1><<<BQ / 4, 256, 82944>>>(emb, w1f, conv_b1);

    lin_kernel<<<BQ / 8, 256>>>(x, lin_w, lin_b);
    deep_kernel<256, 32, 2, 16, 1280><<<BQ / 32, 256>>>(x, dw0, db0, lg0, lb0, h0);
    deep_kernel<128, 64, 4, 8, 256><<<BQ / 64, 256>>>(h0, dw1, db1, lg1, lb1, h1d);
    deep_kernel<64, 128, 8, 4, 128><<<BQ / 128, 256>>>(h1d, dw2, db2, lg2, lb2, out);

    aux_final<<<BQ / 8, 256>>>(cow, cob, out);
}